// round 14
// baseline (speedup 1.0000x reference)
#include <cuda_runtime.h>
#include <cuda_fp16.h>
#include <cstdint>
#include <math.h>

// ---------------- problem constants ----------------
#define B_    8
#define S_    1024
#define HID_  2048
#define H_    16
#define D_    128
#define M_    (B_*S_)      // 8192 token rows
#define FF_   (4*HID_)     // 8192

// weight plane offsets (elements)
#define OFF_Q   0L
#define OFF_K   4194304L
#define OFF_V   8388608L
#define OFF_O   12582912L
#define OFF_W1  16777216L
#define OFF_W2  33554432L
#define W_TOTAL 50331648L

// ---------------- scratch (device globals; no allocations allowed) --------
__device__ float g_acts[(size_t)M_*HID_];
__device__ float g_p0  [(size_t)M_*HID_];   // split-K partial 0
__device__ float g_p1  [(size_t)M_*HID_];   // split-K partial 1
__device__ __half g_qt  [(size_t)M_*HID_];  // [B*H][S][D] fp16
__device__ __half g_kt  [(size_t)M_*HID_];
__device__ __half g_vt  [(size_t)M_*HID_];
__device__ __half g_wh  [W_TOTAL];          // fp16 weights
__device__ __half g_xnh [(size_t)M_*HID_];  // fp16 activations
__device__ __half g_ctxh[(size_t)M_*HID_];
__device__ __half g_hh  [(size_t)M_*FF_];

// ---------------- helpers ---------------------------------------------------
__device__ __forceinline__ uint32_t hx_smem_u32(const void* p) {
    uint32_t a;
    asm("{ .reg .u64 t; cvta.to.shared.u64 t, %1; cvt.u32.u64 %0, t; }" : "=r"(a) : "l"(p));
    return a;
}
#define HX_LDSM4(r, addr) \
    asm volatile("ldmatrix.sync.aligned.m8n8.x4.shared.b16 {%0,%1,%2,%3}, [%4];" \
        : "=r"((r)[0]), "=r"((r)[1]), "=r"((r)[2]), "=r"((r)[3]) : "r"(addr))
#define HX_LDSM4T(r, addr) \
    asm volatile("ldmatrix.sync.aligned.m8n8.x4.trans.shared.b16 {%0,%1,%2,%3}, [%4];" \
        : "=r"((r)[0]), "=r"((r)[1]), "=r"((r)[2]), "=r"((r)[3]) : "r"(addr))

#define HX_MMA(d, a, b0, b1) \
    asm volatile("mma.sync.aligned.m16n8k16.row.col.f32.f16.f16.f32 " \
        "{%0,%1,%2,%3}, {%4,%5,%6,%7}, {%8,%9}, {%0,%1,%2,%3};" \
        : "+f"((d)[0]), "+f"((d)[1]), "+f"((d)[2]), "+f"((d)[3]) \
        : "r"((a)[0]), "r"((a)[1]), "r"((a)[2]), "r"((a)[3]), "r"(b0), "r"(b1))

#define HX_CPASYNC16(dst, src) \
    asm volatile("cp.async.cg.shared.global [%0], [%1], 16;" :: "r"(dst), "l"(src) : "memory")
#define HX_CPCOMMIT() asm volatile("cp.async.commit_group;" ::: "memory")

__device__ __forceinline__ uint32_t hx_pkh(__half a, __half b) {
    __half2 t; t.x = a; t.y = b;
    return *(uint32_t*)&t;
}
__device__ __forceinline__ uint32_t hx_pkf(float a, float b) {
    return hx_pkh(__float2half_rn(a), __float2half_rn(b));
}
__device__ __forceinline__ uint2 hx_cvt4h(float4 v) {
    uint2 h;
    h.x = hx_pkf(v.x, v.y);
    h.y = hx_pkf(v.z, v.w);
    return h;
}

// ---------------- weight fp16 conversion ------------------------------------
__global__ void __launch_bounds__(256) hx_wsplit(
    const float* __restrict__ qw, const float* __restrict__ kw,
    const float* __restrict__ vw, const float* __restrict__ ow,
    const float* __restrict__ w1, const float* __restrict__ w2,
    __half* __restrict__ wh)
{
    const long stride = (long)gridDim.x * blockDim.x;
    for (long i = (long)blockIdx.x * blockDim.x + threadIdx.x;
         i * 4 < W_TOTAL; i += stride) {
        const long e = i * 4;
        const float* src; long off;
        if (e < OFF_W1) {
            const int m = (int)(e >> 22);
            src = (m == 0) ? qw : (m == 1) ? kw : (m == 2) ? vw : ow;
            off = e & 4194303L;
        } else if (e < OFF_W2) { src = w1; off = e - OFF_W1; }
        else                   { src = w2; off = e - OFF_W2; }
        float4 v = *(const float4*)(src + off);
        *(uint2*)(wh + e) = hx_cvt4h(v);
    }
}

// ---------------- fp16 tensor-core GEMM v9 (2 CTAs/SM) ----------------------
// C[M,N] = fp16(A)[M,K] @ fp16(B)[N,K]^T, fp32 accumulate.
// CTA 128x128, 256 threads, 8 warps (4m x 2n), warp tile 32x64.
// K-chunk 64, 3 stages of (A 128x144B + B 128x144B) = 110.6 KB -> 2 CTAs/SM.
// EPI: 0 = split-K partial -> fp32 (Cf/Cf2 by K-half), 2 = exact gelu -> fp16,
//      3 = QKV + xPos rope -> fp16
#define MM4_PL    18432
#define MM4_STAGE (2*MM4_PL)      // 36864
#define MM4_SMEM  (3*MM4_STAGE)   // 110592

template<int EPI>
__global__ void __launch_bounds__(256, 2) mm4(
    int M, int N, int K,
    const __half* __restrict__ Ah,
    const __half* __restrict__ Bh,
    float* __restrict__ Cf, float* __restrict__ Cf2,
    __half* __restrict__ Ch,
    __half* __restrict__ qt, __half* __restrict__ kt, __half* __restrict__ vt,
    const int* __restrict__ pidx,
    int tiles_n)
{
    extern __shared__ char smc[];
    const uint32_t smb = hx_smem_u32(smc);
    const int tid  = threadIdx.x;
    const int lane = tid & 31;
    const int warp = tid >> 5;     // 0..7
    const int wm = warp & 3;       // m offset wm*32
    const int wn = warp >> 2;      // n offset wn*64

    int bx = blockIdx.x;
    int kh = 0;
    if (EPI == 0) { kh = bx & 1; bx >>= 1; }

    // supertile raster: 16 m-tiles per band
    const int SUPER = 16;
    const int per  = SUPER * tiles_n;
    const int band = bx / per;
    const int rem  = bx % per;
    const int mt  = band * SUPER + (rem % SUPER);
    int ntg = rem / SUPER;

    int sel = 0;
    if (EPI == 3) { sel = ntg >> 4; ntg &= 15; }
    const int nt = ntg;

    const long boff = (EPI == 3) ? (long)sel * 4194304L : 0L;
    const long koff = (EPI == 0) ? (long)kh * (K >> 1) : 0L;
    const __half* pAh = Ah + (long)mt * 128 * K + koff;
    const __half* pBh = Bh + boff + (long)nt * 128 * K + koff;

    float acc[2][8][4];
#pragma unroll
    for (int i = 0; i < 2; i++)
#pragma unroll
        for (int j = 0; j < 8; j++)
#pragma unroll
            for (int r = 0; r < 4; r++) acc[i][j][r] = 0.f;

    auto issue_chunk = [&](int c, int st) {
        const uint32_t sb = smb + st * MM4_STAGE;
#pragma unroll
        for (int q = 0; q < 8; q++) {
            const int op = tid + q * 256;        // 0..2047
            const int pl = op >> 10;             // 0=A, 1=B
            const int rm = op & 1023;
            const int r  = rm >> 3;              // 0..127
            const int s  = rm & 7;
            const __half* src = (pl ? pBh : pAh) + (long)r * K + c * 64 + s * 8;
            HX_CPASYNC16(sb + pl * MM4_PL + r * 144 + s * 16, src);
        }
        HX_CPCOMMIT();
    };

    const int nch = ((EPI == 0) ? (K >> 1) : K) / 64;
    issue_chunk(0, 0);
    issue_chunk(1, 1);

    for (int c = 0; c < nch; c++) {
        const int st = c % 3;
        if (c + 1 < nch) { asm volatile("cp.async.wait_group 1;" ::: "memory"); }
        else             { asm volatile("cp.async.wait_group 0;" ::: "memory"); }
        __syncthreads();
        if (c + 2 < nch) issue_chunk(c + 2, (c + 2) % 3);

        const uint32_t stb = smb + st * MM4_STAGE;
#pragma unroll
        for (int ks = 0; ks < 4; ks++) {
            const uint32_t colb = ks * 32 + (lane >> 4) * 16;
            uint32_t ah[2][4], bh[4][4];
#pragma unroll
            for (int im = 0; im < 2; im++) {
                const uint32_t row = wm * 32 + im * 16 + (lane & 15);
                HX_LDSM4(ah[im], stb + row * 144 + colb);
            }
#pragma unroll
            for (int ib = 0; ib < 4; ib++) {
                const uint32_t row = wn * 64 + ib * 16 + (lane & 15);
                HX_LDSM4(bh[ib], stb + MM4_PL + row * 144 + colb);
            }
#pragma unroll
            for (int im = 0; im < 2; im++)
#pragma unroll
                for (int j = 0; j < 8; j++)
                    HX_MMA(acc[im][j], ah[im], bh[j>>1][j&1], bh[j>>1][(j&1)+2]);
        }
    }

    // ---- epilogue ----
    const int pos = (EPI == 3) ? pidx[0] : 0;
    float* Cpart = (EPI == 0) ? (kh ? Cf2 : Cf) : Cf;
#pragma unroll
    for (int im = 0; im < 2; im++)
#pragma unroll
        for (int j = 0; j < 8; j++) {
            const long row0 = (long)mt * 128 + wm * 32 + im * 16 + (lane >> 2);
            const long col  = (long)nt * 128 + wn * 64 + j * 8 + (lane & 3) * 2;
            float2 v0 = { acc[im][j][0], acc[im][j][1] };   // row0,   (col, col+1)
            float2 v1 = { acc[im][j][2], acc[im][j][3] };   // row0+8, (col, col+1)
            if (EPI == 3) {
                const int h = (int)(col >> 7);
                const int d = (int)(col & 127);
                const int s0 = (int)(row0 & 1023), b0 = (int)(row0 >> 10);
                const int s1 = (int)((row0 + 8) & 1023), b1 = (int)((row0 + 8) >> 10);
                const long out0 = (((long)(b0*16 + h))*1024 + s0)*128 + d;
                const long out1 = (((long)(b1*16 + h))*1024 + s1)*128 + d;
                __half* dst = (sel == 0) ? qt : (sel == 1) ? kt : vt;
                if (sel == 0) {
                    *(uint32_t*)(dst + out0) = hx_pkf(v0.x, v0.y);
                    *(uint32_t*)(dst + out1) = hx_pkf(v1.x, v1.y);
                } else {
                    const float df    = 2.0f * (float)((d >> 1) + 1);
                    const float theta = expf(-(df * (1.0f/128.0f)) * 9.210340371976184f);
                    const float lz    = logf((df*(1.0f/64.0f) + 51.2f) * (1.0f/52.2f));
                    const float seq0 = (float)(pos + s0 - 512) * (1.0f/512.0f);
                    const float seq1 = (float)(pos + s1 - 512) * (1.0f/512.0f);
                    float sn0, cs0, sn1, cs1;
                    sincosf(seq0*theta, &sn0, &cs0);
                    sincosf(seq1*theta, &sn1, &cs1);
                    float t0 = expf(seq0*lz), t1 = expf(seq1*lz);
                    if (sel == 2) { t0 = 1.0f/t0; t1 = 1.0f/t1; }
                    const float x0 = (v0.x*cs0 - v0.y*sn0)*t0;
                    const float y0 = (v0.y*cs0 + v0.x*sn0)*t0;
                    const float x1 = (v1.x*cs1 - v1.y*sn1)*t1;
                    const float y1 = (v1.y*cs1 + v1.x*sn1)*t1;
                    *(uint32_t*)(dst + out0) = hx_pkf(x0, y0);
                    *(uint32_t*)(dst + out1) = hx_pkf(x1, y1);
                }
            } else {
                const long o0 = row0 * N + col;
                const long o1 = (row0 + 8) * N + col;
                if (EPI == 2) {
                    v0.x = 0.5f*v0.x*(1.0f + erff(v0.x*0.70710678118654752f));
                    v0.y = 0.5f*v0.y*(1.0f + erff(v0.y*0.70710678118654752f));
                    v1.x = 0.5f*v1.x*(1.0f + erff(v1.x*0.70710678118654752f));
                    v1.y = 0.5f*v1.y*(1.0f + erff(v1.y*0.70710678118654752f));
                    *(uint32_t*)(Ch + o0) = hx_pkf(v0.x, v0.y);
                    *(uint32_t*)(Ch + o1) = hx_pkf(v1.x, v1.y);
                } else {
                    *(float2*)(Cpart + o0) = v0;
                    *(float2*)(Cpart + o1) = v1;
                }
            }
        }
}

// ---------------- LayerNorm -> fp16 plane (LN1) -----------------------------
__global__ void __launch_bounds__(256) hx_ln(const float* __restrict__ x,
                                             const float* __restrict__ w,
                                             __half* __restrict__ outh)
{
    const int row = blockIdx.x;
    const int tid = threadIdx.x;
    const float4* xr = (const float4*)(x + (long)row*HID_);
    float4 a = xr[tid];
    float4 b = xr[tid + 256];
    float s  = a.x+a.y+a.z+a.w + b.x+b.y+b.z+b.w;
    float s2 = a.x*a.x+a.y*a.y+a.z*a.z+a.w*a.w
             + b.x*b.x+b.y*b.y+b.z*b.z+b.w*b.w;
#pragma unroll
    for (int o = 16; o; o >>= 1) {
        s  += __shfl_xor_sync(0xffffffffu, s,  o);
        s2 += __shfl_xor_sync(0xffffffffu, s2, o);
    }
    __shared__ float sh[16];
    if ((tid & 31) == 0) { sh[tid >> 5] = s; sh[(tid >> 5) + 8] = s2; }
    __syncthreads();
    float ts = 0.f, ts2 = 0.f;
#pragma unroll
    for (int i = 0; i < 8; i++) { ts += sh[i]; ts2 += sh[i + 8]; }
    const float mean = ts * (1.0f/HID_);
    const float var  = ts2 * (1.0f/HID_) - mean*mean;
    const float rstd = rsqrtf(var + 1e-5f);

    const float4* wr = (const float4*)w;
    float4 w0 = wr[tid], w1v = wr[tid + 256];
    float4 o0, o1;
    o0.x = (a.x-mean)*rstd*w0.x;  o0.y = (a.y-mean)*rstd*w0.y;
    o0.z = (a.z-mean)*rstd*w0.z;  o0.w = (a.w-mean)*rstd*w0.w;
    o1.x = (b.x-mean)*rstd*w1v.x; o1.y = (b.y-mean)*rstd*w1v.y;
    o1.z = (b.z-mean)*rstd*w1v.z; o1.w = (b.w-mean)*rstd*w1v.w;

    *(uint2*)(outh + (long)row*HID_ + tid*4)       = hx_cvt4h(o0);
    *(uint2*)(outh + (long)row*HID_ + (tid+256)*4) = hx_cvt4h(o1);
}

// -------- combine split-K partials + residual, then LayerNorm (O-proj) ------
__global__ void __launch_bounds__(256) hx_comb_ln(
    const float* __restrict__ p0, const float* __restrict__ p1,
    const float* __restrict__ res, const float* __restrict__ w,
    float* __restrict__ acts, __half* __restrict__ outh)
{
    const int row = blockIdx.x;
    const int tid = threadIdx.x;
    const long base = (long)row*HID_;
    float4 a, b;
    {
        float4 x0 = ((const float4*)(p0 + base))[tid];
        float4 x1 = ((const float4*)(p1 + base))[tid];
        float4 x2 = ((const float4*)(res + base))[tid];
        a.x = x0.x + x1.x + x2.x; a.y = x0.y + x1.y + x2.y;
        a.z = x0.z + x1.z + x2.z; a.w = x0.w + x1.w + x2.w;
        float4 y0 = ((const float4*)(p0 + base))[tid + 256];
        float4 y1 = ((const float4*)(p1 + base))[tid + 256];
        float4 y2 = ((const float4*)(res + base))[tid + 256];
        b.x = y0.x + y1.x + y2.x; b.y = y0.y + y1.y + y2.y;
        b.z = y0.z + y1.z + y2.z; b.w = y0.w + y1.w + y2.w;
    }
    ((float4*)(acts + base))[tid]       = a;
    ((float4*)(acts + base))[tid + 256] = b;

    float s  = a.x+a.y+a.z+a.w + b.x+b.y+b.z+b.w;
    float s2 = a.x*a.x+a.y*a.y+a.z*a.z+a.w*a.w
             + b.x*b.x+b.y*b.y+b.z*b.z+b.w*b.w;
#pragma unroll
    for (int o = 16; o; o >>= 1) {
        s  += __shfl_xor_sync(0xffffffffu, s,  o);
        s2 += __shfl_xor_sync(0xffffffffu, s2, o);
    }
    __shared__ float sh[16];
    if ((tid & 31) == 0) { sh[tid >> 5] = s; sh[(tid >> 5) + 8] = s2; }
    __syncthreads();
    float ts = 0.f, ts2 = 0.f;
#pragma unroll
    for (int i = 0; i < 8; i++) { ts += sh[i]; ts2 += sh[i + 8]; }
    const float mean = ts * (1.0f/HID_);
    const float var  = ts2 * (1.0f/HID_) - mean*mean;
    const float rstd = rsqrtf(var + 1e-5f);

    const float4* wr = (const float4*)w;
    float4 w0 = wr[tid], w1v = wr[tid + 256];
    float4 o0, o1;
    o0.x = (a.x-mean)*rstd*w0.x;  o0.y = (a.y-mean)*rstd*w0.y;
    o0.z = (a.z-mean)*rstd*w0.z;  o0.w = (a.w-mean)*rstd*w0.w;
    o1.x = (b.x-mean)*rstd*w1v.x; o1.y = (b.y-mean)*rstd*w1v.y;
    o1.z = (b.z-mean)*rstd*w1v.z; o1.w = (b.w-mean)*rstd*w1v.w;

    *(uint2*)(outh + base + tid*4)       = hx_cvt4h(o0);
    *(uint2*)(outh + base + (tid+256)*4) = hx_cvt4h(o1);
}

// -------- combine split-K partials + residual -> final output (FFN2) --------
__global__ void __launch_bounds__(256) hx_comb_out(
    const float* __restrict__ p0, const float* __restrict__ p1,
    const float* __restrict__ res, float* __restrict__ out)
{
    const long n4 = (long)M_*HID_/4;
    const long stride = (long)gridDim.x * blockDim.x;
    for (long i = (long)blockIdx.x * blockDim.x + threadIdx.x; i < n4; i += stride) {
        float4 x0 = ((const float4*)p0)[i];
        float4 x1 = ((const float4*)p1)[i];
        float4 x2 = ((const float4*)res)[i];
        float4 v;
        v.x = x0.x + x1.x + x2.x; v.y = x0.y + x1.y + x2.y;
        v.z = x0.z + x1.z + x2.z; v.w = x0.w + x1.w + x2.w;
        ((float4*)out)[i] = v;
    }
}

// ---------------- fp16 tensor-core causal flash attention (3-stage) ---------
#define AT_ROW    272
#define AT_Q      0
#define AT_QBYTES (128*AT_ROW)        // 34816
#define AT_KB     17408               // 64*272
#define AT_STAGE  (2*AT_KB)           // 34816
#define AT_SMEM   (AT_QBYTES + 3*AT_STAGE)  // 139264

__global__ void __launch_bounds__(256, 1) hx_attn16(
    const __half* __restrict__ qt, const __half* __restrict__ kt,
    const __half* __restrict__ vt, __half* __restrict__ ctxh)
{
    extern __shared__ char smc[];
    const uint32_t smb = hx_smem_u32(smc);
    const int tid = threadIdx.x, lane = tid & 31, warp = tid >> 5;
    const int qb = blockIdx.x;
    const int bh = blockIdx.y;
    const int b = bh >> 4, h = bh & 15;
    const int wrow = warp * 16;

    const __half* Qg = qt + ((long)bh*S_ + qb*128)*D_;
    const __half* Kg = kt + (long)bh*S_*D_;
    const __half* Vg = vt + (long)bh*S_*D_;

#pragma unroll
    for (int p = 0; p < 8; p++) {
        const int op = tid + p*256;
        const int r = op >> 4, s = op & 15;
        HX_CPASYNC16(smb + AT_Q + r*AT_ROW + s*16, Qg + (long)r*D_ + s*8);
    }
    auto issue_kv = [&](int j, int st) {
        const uint32_t sb = smb + AT_QBYTES + st*AT_STAGE;
#pragma unroll
        for (int p = 0; p < 8; p++) {
            const int op = tid + p*256;
            const int kv = op >> 10;
            const int rm = op & 1023;
            const int r = rm >> 4, s = rm & 15;
            const __half* src = (kv ? Vg : Kg) + (long)(j*64 + r)*D_ + s*8;
            HX_CPASYNC16(sb + kv*AT_KB + r*AT_ROW + s*16, src);
        }
        HX_CPCOMMIT();
    };

    const int njt = 2*qb + 2;
    issue_kv(0, 0);
    issue_kv(1, 1);
    asm volatile("cp.async.wait_group 1;" ::: "memory");
    __syncthreads();

    uint32_t qf[8][4];
#pragma unroll
    for (int kb = 0; kb < 8; kb++)
        HX_LDSM4(qf[kb], smb + AT_Q + (wrow + (lane & 15))*AT_ROW + kb*32 + (lane >> 4)*16);

    float o[16][4];
#pragma unroll
    for (int nd = 0; nd < 16; nd++)
#pragma unroll
        for (int r = 0; r < 4; r++) o[nd][r] = 0.f;
    float mi0 = -INFINITY, mi1 = -INFINITY, li0 = 0.f, li1 = 0.f;

    const float scale = 0.088388347648318447f;
    const int r0g = qb*128 + wrow + (lane >> 2);
    const int c0l = (lane & 3)*2;

    for (int j = 0; j < njt; j++) {
        const int st = j % 3;
        if (j > 0) {
            if (j + 1 < njt) { asm volatile("cp.async.wait_group 1;" ::: "memory"); }
            else             { asm volatile("cp.async.wait_group 0;" ::: "memory"); }
            __syncthreads();
        }
        // prefetch into the 3rd stage BEFORE compute of this stage
        if (j + 2 < njt) issue_kv(j + 2, (j + 2) % 3);

        const uint32_t kb_ = smb + AT_QBYTES + st*AT_STAGE;
        const uint32_t vb_ = kb_ + AT_KB;

        float sacc[8][4];
#pragma unroll
        for (int nb = 0; nb < 8; nb++)
#pragma unroll
            for (int r = 0; r < 4; r++) sacc[nb][r] = 0.f;
#pragma unroll
        for (int ng = 0; ng < 4; ng++) {
#pragma unroll
            for (int kb = 0; kb < 8; kb++) {
                uint32_t kf[4];
                HX_LDSM4(kf, kb_ + (ng*16 + (lane & 15))*AT_ROW + kb*32 + (lane >> 4)*16);
                HX_MMA(sacc[ng*2+0], qf[kb], kf[0], kf[2]);
                HX_MMA(sacc[ng*2+1], qf[kb], kf[1], kf[3]);
            }
        }

        float rmax0 = -INFINITY, rmax1 = -INFINITY;
#pragma unroll
        for (int nb = 0; nb < 8; nb++) {
            const int cg = j*64 + nb*8 + c0l;
            float v0 = sacc[nb][0]*scale; if (cg     > r0g)     v0 = -INFINITY;
            float v1 = sacc[nb][1]*scale; if (cg + 1 > r0g)     v1 = -INFINITY;
            float v2 = sacc[nb][2]*scale; if (cg     > r0g + 8) v2 = -INFINITY;
            float v3 = sacc[nb][3]*scale; if (cg + 1 > r0g + 8) v3 = -INFINITY;
            sacc[nb][0] = v0; sacc[nb][1] = v1; sacc[nb][2] = v2; sacc[nb][3] = v3;
            rmax0 = fmaxf(rmax0, fmaxf(v0, v1));
            rmax1 = fmaxf(rmax1, fmaxf(v2, v3));
        }
        rmax0 = fmaxf(rmax0, __shfl_xor_sync(0xffffffffu, rmax0, 1));
        rmax0 = fmaxf(rmax0, __shfl_xor_sync(0xffffffffu, rmax0, 2));
        rmax1 = fmaxf(rmax1, __shfl_xor_sync(0xffffffffu, rmax1, 1));
        rmax1 = fmaxf(rmax1, __shfl_xor_sync(0xffffffffu, rmax1, 2));
        const float mn0 = fmaxf(mi0, rmax0), mn1 = fmaxf(mi1, rmax1);
        const float a0 = __expf(mi0 - mn0), a1 = __expf(mi1 - mn1);
        float rs0 = 0.f, rs1 = 0.f;
#pragma unroll
        for (int nb = 0; nb < 8; nb++) {
            const float p0 = __expf(sacc[nb][0] - mn0);
            const float p1 = __expf(sacc[nb][1] - mn0);
            const float p2 = __expf(sacc[nb][2] - mn1);
            const float p3 = __expf(sacc[nb][3] - mn1);
            sacc[nb][0] = p0; sacc[nb][1] = p1; sacc[nb][2] = p2; sacc[nb][3] = p3;
            rs0 += p0 + p1; rs1 += p2 + p3;
        }
        rs0 += __shfl_xor_sync(0xffffffffu, rs0, 1);
        rs0 += __shfl_xor_sync(0xffffffffu, rs0, 2);
        rs1 += __shfl_xor_sync(0xffffffffu, rs1, 1);
        rs1 += __shfl_xor_sync(0xffffffffu, rs1, 2);
        li0 = li0*a0 + rs0; li1 = li1*a1 + rs1;
        mi0 = mn0; mi1 = mn1;
#pragma unroll
        for (int nd = 0; nd < 16; nd++) {
            o[nd][0] *= a0; o[nd][1] *= a0; o[nd][2] *= a1; o[nd][3] *= a1;
        }

        uint32_t pa[4][4];
#pragma unroll
        for (int kk = 0; kk < 4; kk++) {
            pa[kk][0] = hx_pkf(sacc[2*kk][0],   sacc[2*kk][1]);
            pa[kk][1] = hx_pkf(sacc[2*kk][2],   sacc[2*kk][3]);
            pa[kk][2] = hx_pkf(sacc[2*kk+1][0], sacc[2*kk+1][1]);
            pa[kk][3] = hx_pkf(sacc[2*kk+1][2], sacc[2*kk+1][3]);
        }

#pragma unroll
        for (int ndg = 0; ndg < 8; ndg++) {
#pragma unroll
            for (int kk = 0; kk < 4; kk++) {
                uint32_t vf[4];
                HX_LDSM4T(vf, vb_ + (kk*16 + (lane & 15))*AT_ROW + ndg*32 + (lane >> 4)*16);
                HX_MMA(o[ndg*2+0], pa[kk], vf[0], vf[1]);
                HX_MMA(o[ndg*2+1], pa[kk], vf[2], vf[3]);
            }
        }
    }

    const float i0 = 1.f/li0, i1 = 1.f/li1;
    const long s0 = (long)(b*S_) + qb*128 + wrow + (lane >> 2);
    const long base0 = s0*HID_ + h*128 + c0l;
    const long base1 = (s0 + 8)*HID_ + h*128 + c0l;
#pragma unroll
    for (int nd = 0; nd < 16; nd++) {
        *(uint32_t*)(ctxh + base0 + nd*8) = hx_pkf(o[nd][0]*i0, o[nd][1]*i0);
        *(uint32_t*)(ctxh + base1 + nd*8) = hx_pkf(o[nd][2]*i1, o[nd][3]*i1);
    }
}

// ---------------- launch ----------------------------------------------------
extern "C" void kernel_launch(void* const* d_in, const int* in_sizes, int n_in,
                              void* d_out, int out_size)
{
    const float* acts_in = (const float*)d_in[0];
    const float* ln1_w   = (const float*)d_in[4];
    const float* ln2_w   = (const float*)d_in[5];
    const float* q_w     = (const float*)d_in[6];
    const float* k_w     = (const float*)d_in[7];
    const float* v_w     = (const float*)d_in[8];
    const float* o_w     = (const float*)d_in[9];
    const float* w1      = (const float*)d_in[10];
    const float* w2      = (const float*)d_in[11];
    const int*   p_index = (const int*)d_in[3];
    float* out = (float*)d_out;

    float *p_acts, *p_p0, *p_p1;
    __half *p_qt, *p_kt, *p_vt, *p_wh, *p_xnh, *p_ctxh, *p_hh;
    cudaGetSymbolAddress((void**)&p_acts, g_acts);
    cudaGetSymbolAddress((void**)&p_p0,   g_p0);
    cudaGetSymbolAddress((void**)&p_p1,   g_p1);
    cudaGetSymbolAddress((void**)&p_qt,   g_qt);
    cudaGetSymbolAddress((void**)&p_kt,   g_kt);
    cudaGetSymbolAddress((void**)&p_vt,   g_vt);
    cudaGetSymbolAddress((void**)&p_wh,   g_wh);
    cudaGetSymbolAddress((void**)&p_xnh,  g_xnh);
    cudaGetSymbolAddress((void**)&p_ctxh, g_ctxh);
    cudaGetSymbolAddress((void**)&p_hh,   g_hh);

    cudaFuncSetAttribute(mm4<0>, cudaFuncAttributeMaxDynamicSharedMemorySize, MM4_SMEM);
    cudaFuncSetAttribute(mm4<2>, cudaFuncAttributeMaxDynamicSharedMemorySize, MM4_SMEM);
    cudaFuncSetAttribute(mm4<3>, cudaFuncAttributeMaxDynamicSharedMemorySize, MM4_SMEM);
    cudaFuncSetAttribute(hx_attn16, cudaFuncAttributeMaxDynamicSharedMemorySize, AT_SMEM);

    // 0) weight fp16 conversion
    hx_wsplit<<<4096, 256>>>(q_w, k_w, v_w, o_w, w1, w2, p_wh);

    // 1) LN1 -> xn fp16
    hx_ln<<<M_, 256>>>(acts_in, ln1_w, p_xnh);

    // 2) fused QKV projection + xPos rope + transpose -> fp16 qt/kt/vt
    mm4<3><<<64*48, 256, MM4_SMEM>>>(M_, HID_, HID_,
        p_xnh, p_wh, nullptr, nullptr, nullptr,
        p_qt, p_kt, p_vt, p_index, 48);

    // 3) fp16 tensor-core causal flash attention -> ctx fp16
    hx_attn16<<<dim3(S_/128, B_*H_), 256, AT_SMEM>>>(p_qt, p_kt, p_vt, p_ctxh);

    // 4) O projection, split-K x2 -> partials
    mm4<0><<<2*64*16, 256, MM4_SMEM>>>(M_, HID_, HID_,
        p_ctxh, p_wh + OFF_O, p_p0, p_p1, nullptr,
        nullptr, nullptr, nullptr, nullptr, 16);

    // 5) combine + residual + LN2 -> acts fp32 + xn fp16
    hx_comb_ln<<<M_, 256>>>(p_p0, p_p1, acts_in, ln2_w, p_acts, p_xnh);

    // 6) FFN up + exact GELU -> h fp16
    mm4<2><<<64*64, 256, MM4_SMEM>>>(M_, FF_, HID_,
        p_xnh, p_wh + OFF_W1, nullptr, nullptr, p_hh,
        nullptr, nullptr, nullptr, nullptr, 64);

    // 7) FFN down, split-K x2 -> partials
    mm4<0><<<2*64*16, 256, MM4_SMEM>>>(M_, HID_, FF_,
        p_hh, p_wh + OFF_W2, p_p0, p_p1, nullptr,
        nullptr, nullptr, nullptr, nullptr, 16);

    // 8) combine + residual -> output acts
    hx_comb_out<<<2048, 256>>>(p_p0, p_p1, p_acts, out);

    // 9) pass-through caches
    const long actN = (long)M_*HID_;
    if (n_in > 2 && (long)out_size >= actN + (long)in_sizes[1] + (long)in_sizes[2]) {
        cudaMemcpyAsync(out + actN, d_in[1],
                        (size_t)in_sizes[1]*sizeof(float),
                        cudaMemcpyDeviceToDevice);
        cudaMemcpyAsync(out + actN + in_sizes[1], d_in[2],
                        (size_t)in_sizes[2]*sizeof(float),
                        cudaMemcpyDeviceToDevice);
    }
}

// round 15
// speedup vs baseline: 1.0234x; 1.0234x over previous
#include <cuda_runtime.h>
#include <cuda_fp16.h>
#include <cstdint>
#include <math.h>

// ---------------- problem constants ----------------
#define B_    8
#define S_    1024
#define HID_  2048
#define H_    16
#define D_    128
#define M_    (B_*S_)      // 8192 token rows
#define FF_   (4*HID_)     // 8192

// weight plane offsets (elements)
#define OFF_Q   0L
#define OFF_K   4194304L
#define OFF_V   8388608L
#define OFF_O   12582912L
#define OFF_W1  16777216L
#define OFF_W2  33554432L
#define W_TOTAL 50331648L

// ---------------- scratch (device globals; no allocations allowed) --------
__device__ float g_acts[(size_t)M_*HID_];
__device__ __half g_qt  [(size_t)M_*HID_];  // [B*H][S][D] fp16
__device__ __half g_kt  [(size_t)M_*HID_];
__device__ __half g_vt  [(size_t)M_*HID_];
__device__ __half g_wh  [W_TOTAL];          // fp16 weights
__device__ __half g_xnh [(size_t)M_*HID_];  // fp16 activations
__device__ __half g_ctxh[(size_t)M_*HID_];
__device__ __half g_hh  [(size_t)M_*FF_];

// ---------------- helpers ---------------------------------------------------
__device__ __forceinline__ uint32_t hx_smem_u32(const void* p) {
    uint32_t a;
    asm("{ .reg .u64 t; cvta.to.shared.u64 t, %1; cvt.u32.u64 %0, t; }" : "=r"(a) : "l"(p));
    return a;
}
#define HX_LDSM4(r, addr) \
    asm volatile("ldmatrix.sync.aligned.m8n8.x4.shared.b16 {%0,%1,%2,%3}, [%4];" \
        : "=r"((r)[0]), "=r"((r)[1]), "=r"((r)[2]), "=r"((r)[3]) : "r"(addr))
#define HX_LDSM4T(r, addr) \
    asm volatile("ldmatrix.sync.aligned.m8n8.x4.trans.shared.b16 {%0,%1,%2,%3}, [%4];" \
        : "=r"((r)[0]), "=r"((r)[1]), "=r"((r)[2]), "=r"((r)[3]) : "r"(addr))

#define HX_MMA(d, a, b0, b1) \
    asm volatile("mma.sync.aligned.m16n8k16.row.col.f32.f16.f16.f32 " \
        "{%0,%1,%2,%3}, {%4,%5,%6,%7}, {%8,%9}, {%0,%1,%2,%3};" \
        : "+f"((d)[0]), "+f"((d)[1]), "+f"((d)[2]), "+f"((d)[3]) \
        : "r"((a)[0]), "r"((a)[1]), "r"((a)[2]), "r"((a)[3]), "r"(b0), "r"(b1))

#define HX_CPASYNC16(dst, src) \
    asm volatile("cp.async.cg.shared.global [%0], [%1], 16;" :: "r"(dst), "l"(src) : "memory")
#define HX_CPCOMMIT() asm volatile("cp.async.commit_group;" ::: "memory")

__device__ __forceinline__ uint32_t hx_pkh(__half a, __half b) {
    __half2 t; t.x = a; t.y = b;
    return *(uint32_t*)&t;
}
__device__ __forceinline__ uint32_t hx_pkf(float a, float b) {
    return hx_pkh(__float2half_rn(a), __float2half_rn(b));
}
__device__ __forceinline__ uint2 hx_cvt4h(float4 v) {
    uint2 h;
    h.x = hx_pkf(v.x, v.y);
    h.y = hx_pkf(v.z, v.w);
    return h;
}

// ---------------- weight fp16 conversion ------------------------------------
__global__ void __launch_bounds__(256) hx_wsplit(
    const float* __restrict__ qw, const float* __restrict__ kw,
    const float* __restrict__ vw, const float* __restrict__ ow,
    const float* __restrict__ w1, const float* __restrict__ w2,
    __half* __restrict__ wh)
{
    const long stride = (long)gridDim.x * blockDim.x;
    for (long i = (long)blockIdx.x * blockDim.x + threadIdx.x;
         i * 4 < W_TOTAL; i += stride) {
        const long e = i * 4;
        const float* src; long off;
        if (e < OFF_W1) {
            const int m = (int)(e >> 22);
            src = (m == 0) ? qw : (m == 1) ? kw : (m == 2) ? vw : ow;
            off = e & 4194303L;
        } else if (e < OFF_W2) { src = w1; off = e - OFF_W1; }
        else                   { src = w2; off = e - OFF_W2; }
        float4 v = *(const float4*)(src + off);
        *(uint2*)(wh + e) = hx_cvt4h(v);
    }
}

// ---------------- fp16 tensor-core GEMM v8 (2 CTAs/SM) ----------------------
// C[M,N] = fp16(A)[M,K] @ fp16(B)[N,K]^T, fp32 accumulate.
// CTA 128x128, 256 threads, 8 warps (4m x 2n), warp tile 32x64.
// K-chunk 64, 3 stages of (A 128x144B + B 128x144B) = 110.6 KB -> 2 CTAs/SM.
// EPI: 1 = +Res -> fp32 C, 2 = exact gelu -> fp16, 3 = QKV + xPos rope -> fp16
#define MM4_PL    18432
#define MM4_STAGE (2*MM4_PL)      // 36864
#define MM4_SMEM  (3*MM4_STAGE)   // 110592

template<int EPI>
__global__ void __launch_bounds__(256, 2) mm4(
    int M, int N, int K,
    const __half* __restrict__ Ah,
    const __half* __restrict__ Bh,
    const float* __restrict__ Res,
    float* __restrict__ Cf,
    __half* __restrict__ Ch,
    __half* __restrict__ qt, __half* __restrict__ kt, __half* __restrict__ vt,
    const int* __restrict__ pidx,
    int tiles_n)
{
    extern __shared__ char smc[];
    const uint32_t smb = hx_smem_u32(smc);
    const int tid  = threadIdx.x;
    const int lane = tid & 31;
    const int warp = tid >> 5;     // 0..7
    const int wm = warp & 3;       // m offset wm*32
    const int wn = warp >> 2;      // n offset wn*64

    // supertile raster: 16 m-tiles per band
    const int SUPER = 16;
    const int per  = SUPER * tiles_n;
    const int band = blockIdx.x / per;
    const int rem  = blockIdx.x % per;
    const int mt  = band * SUPER + (rem % SUPER);
    int ntg = rem / SUPER;

    int sel = 0;
    if (EPI == 3) { sel = ntg >> 4; ntg &= 15; }
    const int nt = ntg;

    const long boff = (EPI == 3) ? (long)sel * 4194304L : 0L;
    const __half* pAh = Ah + (long)mt * 128 * K;
    const __half* pBh = Bh + boff + (long)nt * 128 * K;

    float acc[2][8][4];
#pragma unroll
    for (int i = 0; i < 2; i++)
#pragma unroll
        for (int j = 0; j < 8; j++)
#pragma unroll
            for (int r = 0; r < 4; r++) acc[i][j][r] = 0.f;

    auto issue_chunk = [&](int c, int st) {
        const uint32_t sb = smb + st * MM4_STAGE;
#pragma unroll
        for (int q = 0; q < 8; q++) {
            const int op = tid + q * 256;        // 0..2047
            const int pl = op >> 10;             // 0=A, 1=B
            const int rm = op & 1023;
            const int r  = rm >> 3;              // 0..127
            const int s  = rm & 7;
            const __half* src = (pl ? pBh : pAh) + (long)r * K + c * 64 + s * 8;
            HX_CPASYNC16(sb + pl * MM4_PL + r * 144 + s * 16, src);
        }
        HX_CPCOMMIT();
    };

    const int nch = K / 64;
    issue_chunk(0, 0);
    issue_chunk(1, 1);

    for (int c = 0; c < nch; c++) {
        const int st = c % 3;
        if (c + 1 < nch) { asm volatile("cp.async.wait_group 1;" ::: "memory"); }
        else             { asm volatile("cp.async.wait_group 0;" ::: "memory"); }
        __syncthreads();
        if (c + 2 < nch) issue_chunk(c + 2, (c + 2) % 3);

        const uint32_t stb = smb + st * MM4_STAGE;
#pragma unroll
        for (int ks = 0; ks < 4; ks++) {
            const uint32_t colb = ks * 32 + (lane >> 4) * 16;
            uint32_t ah[2][4], bh[4][4];
#pragma unroll
            for (int im = 0; im < 2; im++) {
                const uint32_t row = wm * 32 + im * 16 + (lane & 15);
                HX_LDSM4(ah[im], stb + row * 144 + colb);
            }
#pragma unroll
            for (int ib = 0; ib < 4; ib++) {
                const uint32_t row = wn * 64 + ib * 16 + (lane & 15);
                HX_LDSM4(bh[ib], stb + MM4_PL + row * 144 + colb);
            }
#pragma unroll
            for (int im = 0; im < 2; im++)
#pragma unroll
                for (int j = 0; j < 8; j++)
                    HX_MMA(acc[im][j], ah[im], bh[j>>1][j&1], bh[j>>1][(j&1)+2]);
        }
    }

    // ---- epilogue ----
    const int pos = (EPI == 3) ? pidx[0] : 0;
#pragma unroll
    for (int im = 0; im < 2; im++)
#pragma unroll
        for (int j = 0; j < 8; j++) {
            const long row0 = (long)mt * 128 + wm * 32 + im * 16 + (lane >> 2);
            const long col  = (long)nt * 128 + wn * 64 + j * 8 + (lane & 3) * 2;
            float2 v0 = { acc[im][j][0], acc[im][j][1] };   // row0,   (col, col+1)
            float2 v1 = { acc[im][j][2], acc[im][j][3] };   // row0+8, (col, col+1)
            if (EPI == 3) {
                const int h = (int)(col >> 7);
                const int d = (int)(col & 127);
                const int s0 = (int)(row0 & 1023), b0 = (int)(row0 >> 10);
                const int s1 = (int)((row0 + 8) & 1023), b1 = (int)((row0 + 8) >> 10);
                const long out0 = (((long)(b0*16 + h))*1024 + s0)*128 + d;
                const long out1 = (((long)(b1*16 + h))*1024 + s1)*128 + d;
                __half* dst = (sel == 0) ? qt : (sel == 1) ? kt : vt;
                if (sel == 0) {
                    *(uint32_t*)(dst + out0) = hx_pkf(v0.x, v0.y);
                    *(uint32_t*)(dst + out1) = hx_pkf(v1.x, v1.y);
                } else {
                    const float df    = 2.0f * (float)((d >> 1) + 1);
                    const float theta = __expf(-(df * (1.0f/128.0f)) * 9.210340371976184f);
                    const float lz    = __logf((df*(1.0f/64.0f) + 51.2f) * (1.0f/52.2f));
                    const float seq0 = (float)(pos + s0 - 512) * (1.0f/512.0f);
                    const float seq1 = (float)(pos + s1 - 512) * (1.0f/512.0f);
                    float sn0, cs0, sn1, cs1;
                    __sincosf(seq0*theta, &sn0, &cs0);
                    __sincosf(seq1*theta, &sn1, &cs1);
                    float t0 = __expf(seq0*lz), t1 = __expf(seq1*lz);
                    if (sel == 2) { t0 = 1.0f/t0; t1 = 1.0f/t1; }
                    const float x0 = (v0.x*cs0 - v0.y*sn0)*t0;
                    const float y0 = (v0.y*cs0 + v0.x*sn0)*t0;
                    const float x1 = (v1.x*cs1 - v1.y*sn1)*t1;
                    const float y1 = (v1.y*cs1 + v1.x*sn1)*t1;
                    *(uint32_t*)(dst + out0) = hx_pkf(x0, y0);
                    *(uint32_t*)(dst + out1) = hx_pkf(x1, y1);
                }
            } else {
                const long o0 = row0 * N + col;
                const long o1 = (row0 + 8) * N + col;
                if (EPI == 2) {
                    v0.x = 0.5f*v0.x*(1.0f + erff(v0.x*0.70710678118654752f));
                    v0.y = 0.5f*v0.y*(1.0f + erff(v0.y*0.70710678118654752f));
                    v1.x = 0.5f*v1.x*(1.0f + erff(v1.x*0.70710678118654752f));
                    v1.y = 0.5f*v1.y*(1.0f + erff(v1.y*0.70710678118654752f));
                    *(uint32_t*)(Ch + o0) = hx_pkf(v0.x, v0.y);
                    *(uint32_t*)(Ch + o1) = hx_pkf(v1.x, v1.y);
                } else {
                    const float2 r0 = *(const float2*)(Res + o0);
                    const float2 r1 = *(const float2*)(Res + o1);
                    v0.x += r0.x; v0.y += r0.y; v1.x += r1.x; v1.y += r1.y;
                    *(float2*)(Cf + o0) = v0;
                    *(float2*)(Cf + o1) = v1;
                }
            }
        }
}

// ---------------- LayerNorm -> fp16 plane -----------------------------------
__global__ void __launch_bounds__(256) hx_ln(const float* __restrict__ x,
                                             const float* __restrict__ w,
                                             __half* __restrict__ outh)
{
    const int row = blockIdx.x;
    const int tid = threadIdx.x;
    const float4* xr = (const float4*)(x + (long)row*HID_);
    float4 a = xr[tid];
    float4 b = xr[tid + 256];
    float s  = a.x+a.y+a.z+a.w + b.x+b.y+b.z+b.w;
    float s2 = a.x*a.x+a.y*a.y+a.z*a.z+a.w*a.w
             + b.x*b.x+b.y*b.y+b.z*b.z+b.w*b.w;
#pragma unroll
    for (int o = 16; o; o >>= 1) {
        s  += __shfl_xor_sync(0xffffffffu, s,  o);
        s2 += __shfl_xor_sync(0xffffffffu, s2, o);
    }
    __shared__ float sh[16];
    if ((tid & 31) == 0) { sh[tid >> 5] = s; sh[(tid >> 5) + 8] = s2; }
    __syncthreads();
    float ts = 0.f, ts2 = 0.f;
#pragma unroll
    for (int i = 0; i < 8; i++) { ts += sh[i]; ts2 += sh[i + 8]; }
    const float mean = ts * (1.0f/HID_);
    const float var  = ts2 * (1.0f/HID_) - mean*mean;
    const float rstd = rsqrtf(var + 1e-5f);

    const float4* wr = (const float4*)w;
    float4 w0 = wr[tid], w1v = wr[tid + 256];
    float4 o0, o1;
    o0.x = (a.x-mean)*rstd*w0.x;  o0.y = (a.y-mean)*rstd*w0.y;
    o0.z = (a.z-mean)*rstd*w0.z;  o0.w = (a.w-mean)*rstd*w0.w;
    o1.x = (b.x-mean)*rstd*w1v.x; o1.y = (b.y-mean)*rstd*w1v.y;
    o1.z = (b.z-mean)*rstd*w1v.z; o1.w = (b.w-mean)*rstd*w1v.w;

    *(uint2*)(outh + (long)row*HID_ + tid*4)       = hx_cvt4h(o0);
    *(uint2*)(outh + (long)row*HID_ + (tid+256)*4) = hx_cvt4h(o1);
}

// ---------------- fp16 tensor-core causal flash attention (3-stage) ---------
#define AT_ROW    272
#define AT_Q      0
#define AT_QBYTES (128*AT_ROW)        // 34816
#define AT_KB     17408               // 64*272
#define AT_STAGE  (2*AT_KB)           // 34816
#define AT_SMEM   (AT_QBYTES + 3*AT_STAGE)  // 139264

__global__ void __launch_bounds__(256, 1) hx_attn16(
    const __half* __restrict__ qt, const __half* __restrict__ kt,
    const __half* __restrict__ vt, __half* __restrict__ ctxh)
{
    extern __shared__ char smc[];
    const uint32_t smb = hx_smem_u32(smc);
    const int tid = threadIdx.x, lane = tid & 31, warp = tid >> 5;
    const int qb = blockIdx.x;
    const int bh = blockIdx.y;
    const int b = bh >> 4, h = bh & 15;
    const int wrow = warp * 16;

    const __half* Qg = qt + ((long)bh*S_ + qb*128)*D_;
    const __half* Kg = kt + (long)bh*S_*D_;
    const __half* Vg = vt + (long)bh*S_*D_;

#pragma unroll
    for (int p = 0; p < 8; p++) {
        const int op = tid + p*256;
        const int r = op >> 4, s = op & 15;
        HX_CPASYNC16(smb + AT_Q + r*AT_ROW + s*16, Qg + (long)r*D_ + s*8);
    }
    auto issue_kv = [&](int j, int st) {
        const uint32_t sb = smb + AT_QBYTES + st*AT_STAGE;
#pragma unroll
        for (int p = 0; p < 8; p++) {
            const int op = tid + p*256;
            const int kv = op >> 10;
            const int rm = op & 1023;
            const int r = rm >> 4, s = rm & 15;
            const __half* src = (kv ? Vg : Kg) + (long)(j*64 + r)*D_ + s*8;
            HX_CPASYNC16(sb + kv*AT_KB + r*AT_ROW + s*16, src);
        }
        HX_CPCOMMIT();
    };

    const int njt = 2*qb + 2;
    issue_kv(0, 0);
    issue_kv(1, 1);
    asm volatile("cp.async.wait_group 1;" ::: "memory");
    __syncthreads();

    uint32_t qf[8][4];
#pragma unroll
    for (int kb = 0; kb < 8; kb++)
        HX_LDSM4(qf[kb], smb + AT_Q + (wrow + (lane & 15))*AT_ROW + kb*32 + (lane >> 4)*16);

    float o[16][4];
#pragma unroll
    for (int nd = 0; nd < 16; nd++)
#pragma unroll
        for (int r = 0; r < 4; r++) o[nd][r] = 0.f;
    float mi0 = -INFINITY, mi1 = -INFINITY, li0 = 0.f, li1 = 0.f;

    const float scale = 0.088388347648318447f;
    const int r0g = qb*128 + wrow + (lane >> 2);
    const int c0l = (lane & 3)*2;

    for (int j = 0; j < njt; j++) {
        const int st = j % 3;
        if (j > 0) {
            if (j + 1 < njt) { asm volatile("cp.async.wait_group 1;" ::: "memory"); }
            else             { asm volatile("cp.async.wait_group 0;" ::: "memory"); }
            __syncthreads();
        }
        // prefetch into the 3rd stage BEFORE compute of this stage
        if (j + 2 < njt) issue_kv(j + 2, (j + 2) % 3);

        const uint32_t kb_ = smb + AT_QBYTES + st*AT_STAGE;
        const uint32_t vb_ = kb_ + AT_KB;

        float sacc[8][4];
#pragma unroll
        for (int nb = 0; nb < 8; nb++)
#pragma unroll
            for (int r = 0; r < 4; r++) sacc[nb][r] = 0.f;
#pragma unroll
        for (int ng = 0; ng < 4; ng++) {
#pragma unroll
            for (int kb = 0; kb < 8; kb++) {
                uint32_t kf[4];
                HX_LDSM4(kf, kb_ + (ng*16 + (lane & 15))*AT_ROW + kb*32 + (lane >> 4)*16);
                HX_MMA(sacc[ng*2+0], qf[kb], kf[0], kf[2]);
                HX_MMA(sacc[ng*2+1], qf[kb], kf[1], kf[3]);
            }
        }

        float rmax0 = -INFINITY, rmax1 = -INFINITY;
#pragma unroll
        for (int nb = 0; nb < 8; nb++) {
            const int cg = j*64 + nb*8 + c0l;
            float v0 = sacc[nb][0]*scale; if (cg     > r0g)     v0 = -INFINITY;
            float v1 = sacc[nb][1]*scale; if (cg + 1 > r0g)     v1 = -INFINITY;
            float v2 = sacc[nb][2]*scale; if (cg     > r0g + 8) v2 = -INFINITY;
            float v3 = sacc[nb][3]*scale; if (cg + 1 > r0g + 8) v3 = -INFINITY;
            sacc[nb][0] = v0; sacc[nb][1] = v1; sacc[nb][2] = v2; sacc[nb][3] = v3;
            rmax0 = fmaxf(rmax0, fmaxf(v0, v1));
            rmax1 = fmaxf(rmax1, fmaxf(v2, v3));
        }
        rmax0 = fmaxf(rmax0, __shfl_xor_sync(0xffffffffu, rmax0, 1));
        rmax0 = fmaxf(rmax0, __shfl_xor_sync(0xffffffffu, rmax0, 2));
        rmax1 = fmaxf(rmax1, __shfl_xor_sync(0xffffffffu, rmax1, 1));
        rmax1 = fmaxf(rmax1, __shfl_xor_sync(0xffffffffu, rmax1, 2));
        const float mn0 = fmaxf(mi0, rmax0), mn1 = fmaxf(mi1, rmax1);
        const float a0 = __expf(mi0 - mn0), a1 = __expf(mi1 - mn1);
        float rs0 = 0.f, rs1 = 0.f;
#pragma unroll
        for (int nb = 0; nb < 8; nb++) {
            const float p0 = __expf(sacc[nb][0] - mn0);
            const float p1 = __expf(sacc[nb][1] - mn0);
            const float p2 = __expf(sacc[nb][2] - mn1);
            const float p3 = __expf(sacc[nb][3] - mn1);
            sacc[nb][0] = p0; sacc[nb][1] = p1; sacc[nb][2] = p2; sacc[nb][3] = p3;
            rs0 += p0 + p1; rs1 += p2 + p3;
        }
        rs0 += __shfl_xor_sync(0xffffffffu, rs0, 1);
        rs0 += __shfl_xor_sync(0xffffffffu, rs0, 2);
        rs1 += __shfl_xor_sync(0xffffffffu, rs1, 1);
        rs1 += __shfl_xor_sync(0xffffffffu, rs1, 2);
        li0 = li0*a0 + rs0; li1 = li1*a1 + rs1;
        mi0 = mn0; mi1 = mn1;
#pragma unroll
        for (int nd = 0; nd < 16; nd++) {
            o[nd][0] *= a0; o[nd][1] *= a0; o[nd][2] *= a1; o[nd][3] *= a1;
        }

        uint32_t pa[4][4];
#pragma unroll
        for (int kk = 0; kk < 4; kk++) {
            pa[kk][0] = hx_pkf(sacc[2*kk][0],   sacc[2*kk][1]);
            pa[kk][1] = hx_pkf(sacc[2*kk][2],   sacc[2*kk][3]);
            pa[kk][2] = hx_pkf(sacc[2*kk+1][0], sacc[2*kk+1][1]);
            pa[kk][3] = hx_pkf(sacc[2*kk+1][2], sacc[2*kk+1][3]);
        }

#pragma unroll
        for (int ndg = 0; ndg < 8; ndg++) {
#pragma unroll
            for (int kk = 0; kk < 4; kk++) {
                uint32_t vf[4];
                HX_LDSM4T(vf, vb_ + (kk*16 + (lane & 15))*AT_ROW + ndg*32 + (lane >> 4)*16);
                HX_MMA(o[ndg*2+0], pa[kk], vf[0], vf[1]);
                HX_MMA(o[ndg*2+1], pa[kk], vf[2], vf[3]);
            }
        }
    }

    const float i0 = 1.f/li0, i1 = 1.f/li1;
    const long s0 = (long)(b*S_) + qb*128 + wrow + (lane >> 2);
    const long base0 = s0*HID_ + h*128 + c0l;
    const long base1 = (s0 + 8)*HID_ + h*128 + c0l;
#pragma unroll
    for (int nd = 0; nd < 16; nd++) {
        *(uint32_t*)(ctxh + base0 + nd*8) = hx_pkf(o[nd][0]*i0, o[nd][1]*i0);
        *(uint32_t*)(ctxh + base1 + nd*8) = hx_pkf(o[nd][2]*i1, o[nd][3]*i1);
    }
}

// ---------------- launch ----------------------------------------------------
extern "C" void kernel_launch(void* const* d_in, const int* in_sizes, int n_in,
                              void* d_out, int out_size)
{
    const float* acts_in = (const float*)d_in[0];
    const float* ln1_w   = (const float*)d_in[4];
    const float* ln2_w   = (const float*)d_in[5];
    const float* q_w     = (const float*)d_in[6];
    const float* k_w     = (const float*)d_in[7];
    const float* v_w     = (const float*)d_in[8];
    const float* o_w     = (const float*)d_in[9];
    const float* w1      = (const float*)d_in[10];
    const float* w2      = (const float*)d_in[11];
    const int*   p_index = (const int*)d_in[3];
    float* out = (float*)d_out;

    float *p_acts;
    __half *p_qt, *p_kt, *p_vt, *p_wh, *p_xnh, *p_ctxh, *p_hh;
    cudaGetSymbolAddress((void**)&p_acts, g_acts);
    cudaGetSymbolAddress((void**)&p_qt,   g_qt);
    cudaGetSymbolAddress((void**)&p_kt,   g_kt);
    cudaGetSymbolAddress((void**)&p_vt,   g_vt);
    cudaGetSymbolAddress((void**)&p_wh,   g_wh);
    cudaGetSymbolAddress((void**)&p_xnh,  g_xnh);
    cudaGetSymbolAddress((void**)&p_ctxh, g_ctxh);
    cudaGetSymbolAddress((void**)&p_hh,   g_hh);

    cudaFuncSetAttribute(mm4<1>, cudaFuncAttributeMaxDynamicSharedMemorySize, MM4_SMEM);
    cudaFuncSetAttribute(mm4<2>, cudaFuncAttributeMaxDynamicSharedMemorySize, MM4_SMEM);
    cudaFuncSetAttribute(mm4<3>, cudaFuncAttributeMaxDynamicSharedMemorySize, MM4_SMEM);
    cudaFuncSetAttribute(hx_attn16, cudaFuncAttributeMaxDynamicSharedMemorySize, AT_SMEM);

    // 0) weight fp16 conversion
    hx_wsplit<<<4096, 256>>>(q_w, k_w, v_w, o_w, w1, w2, p_wh);

    // 1) LN1 -> xn fp16
    hx_ln<<<M_, 256>>>(acts_in, ln1_w, p_xnh);

    // 2) fused QKV projection + xPos rope + transpose -> fp16 qt/kt/vt
    mm4<3><<<64*48, 256, MM4_SMEM>>>(M_, HID_, HID_,
        p_xnh, p_wh, nullptr, nullptr, nullptr,
        p_qt, p_kt, p_vt, p_index, 48);

    // 3) fp16 tensor-core causal flash attention -> ctx fp16
    hx_attn16<<<dim3(S_/128, B_*H_), 256, AT_SMEM>>>(p_qt, p_kt, p_vt, p_ctxh);

    // 4) O projection + residual -> acts fp32
    mm4<1><<<64*16, 256, MM4_SMEM>>>(M_, HID_, HID_,
        p_ctxh, p_wh + OFF_O, acts_in, p_acts, nullptr,
        nullptr, nullptr, nullptr, nullptr, 16);

    // 5) LN2 -> xn fp16 (reuse)
    hx_ln<<<M_, 256>>>(p_acts, ln2_w, p_xnh);

    // 6) FFN up + exact GELU -> h fp16
    mm4<2><<<64*64, 256, MM4_SMEM>>>(M_, FF_, HID_,
        p_xnh, p_wh + OFF_W1, nullptr, nullptr, p_hh,
        nullptr, nullptr, nullptr, nullptr, 64);

    // 7) FFN down + residual -> output acts
    mm4<1><<<64*16, 256, MM4_SMEM>>>(M_, HID_, FF_,
        p_hh, p_wh + OFF_W2, p_acts, out, nullptr,
        nullptr, nullptr, nullptr, nullptr, 16);

    // 8) pass-through caches
    const long actN = (long)M_*HID_;
    if (n_in > 2 && (long)out_size >= actN + (long)in_sizes[1] + (long)in_sizes[2]) {
        cudaMemcpyAsync(out + actN, d_in[1],
                        (size_t)in_sizes[1]*sizeof(float),
                        cudaMemcpyDeviceToDevice);
        cudaMemcpyAsync(out + actN + in_sizes[1], d_in[2],
                        (size_t)in_sizes[2]*sizeof(float),
                        cudaMemcpyDeviceToDevice);
    }
}

// round 16
// speedup vs baseline: 1.0314x; 1.0078x over previous
#include <cuda_runtime.h>
#include <cuda_fp16.h>
#include <cstdint>
#include <math.h>

// ---------------- problem constants ----------------
#define B_    8
#define S_    1024
#define HID_  2048
#define H_    16
#define D_    128
#define M_    (B_*S_)      // 8192 token rows
#define FF_   (4*HID_)     // 8192

// weight plane offsets (elements)
#define OFF_Q   0L
#define OFF_K   4194304L
#define OFF_V   8388608L
#define OFF_O   12582912L
#define OFF_W1  16777216L
#define OFF_W2  33554432L
#define W_TOTAL 50331648L

// ---------------- scratch (device globals; no allocations allowed) --------
__device__ float g_acts[(size_t)M_*HID_];
__device__ __half g_qt  [(size_t)M_*HID_];  // [B*H][S][D] fp16
__device__ __half g_kt  [(size_t)M_*HID_];
__device__ __half g_vt  [(size_t)M_*HID_];
__device__ __half g_wh  [W_TOTAL];          // fp16 weights
__device__ __half g_xnh [(size_t)M_*HID_];  // fp16 activations
__device__ __half g_ctxh[(size_t)M_*HID_];
__device__ __half g_hh  [(size_t)M_*FF_];

// ---------------- helpers ---------------------------------------------------
__device__ __forceinline__ uint32_t hx_smem_u32(const void* p) {
    uint32_t a;
    asm("{ .reg .u64 t; cvta.to.shared.u64 t, %1; cvt.u32.u64 %0, t; }" : "=r"(a) : "l"(p));
    return a;
}
#define HX_LDSM4(r, addr) \
    asm volatile("ldmatrix.sync.aligned.m8n8.x4.shared.b16 {%0,%1,%2,%3}, [%4];" \
        : "=r"((r)[0]), "=r"((r)[1]), "=r"((r)[2]), "=r"((r)[3]) : "r"(addr))
#define HX_LDSM4T(r, addr) \
    asm volatile("ldmatrix.sync.aligned.m8n8.x4.trans.shared.b16 {%0,%1,%2,%3}, [%4];" \
        : "=r"((r)[0]), "=r"((r)[1]), "=r"((r)[2]), "=r"((r)[3]) : "r"(addr))

#define HX_MMA(d, a, b0, b1) \
    asm volatile("mma.sync.aligned.m16n8k16.row.col.f32.f16.f16.f32 " \
        "{%0,%1,%2,%3}, {%4,%5,%6,%7}, {%8,%9}, {%0,%1,%2,%3};" \
        : "+f"((d)[0]), "+f"((d)[1]), "+f"((d)[2]), "+f"((d)[3]) \
        : "r"((a)[0]), "r"((a)[1]), "r"((a)[2]), "r"((a)[3]), "r"(b0), "r"(b1))

#define HX_CPASYNC16(dst, src) \
    asm volatile("cp.async.cg.shared.global [%0], [%1], 16;" :: "r"(dst), "l"(src) : "memory")
#define HX_CPCOMMIT() asm volatile("cp.async.commit_group;" ::: "memory")

__device__ __forceinline__ uint32_t hx_pkh(__half a, __half b) {
    __half2 t; t.x = a; t.y = b;
    return *(uint32_t*)&t;
}
__device__ __forceinline__ uint32_t hx_pkf(float a, float b) {
    return hx_pkh(__float2half_rn(a), __float2half_rn(b));
}
__device__ __forceinline__ uint2 hx_cvt4h(float4 v) {
    uint2 h;
    h.x = hx_pkf(v.x, v.y);
    h.y = hx_pkf(v.z, v.w);
    return h;
}

// ---------------- weight fp16 conversion ------------------------------------
__global__ void __launch_bounds__(256) hx_wsplit(
    const float* __restrict__ qw, const float* __restrict__ kw,
    const float* __restrict__ vw, const float* __restrict__ ow,
    const float* __restrict__ w1, const float* __restrict__ w2,
    __half* __restrict__ wh)
{
    const long stride = (long)gridDim.x * blockDim.x;
    for (long i = (long)blockIdx.x * blockDim.x + threadIdx.x;
         i * 4 < W_TOTAL; i += stride) {
        const long e = i * 4;
        const float* src; long off;
        if (e < OFF_W1) {
            const int m = (int)(e >> 22);
            src = (m == 0) ? qw : (m == 1) ? kw : (m == 2) ? vw : ow;
            off = e & 4194303L;
        } else if (e < OFF_W2) { src = w1; off = e - OFF_W1; }
        else                   { src = w2; off = e - OFF_W2; }
        float4 v = *(const float4*)(src + off);
        *(uint2*)(wh + e) = hx_cvt4h(v);
    }
}

// ---------------- fp16 tensor-core GEMM v8 (2 CTAs/SM) ----------------------
// C[M,N] = fp16(A)[M,K] @ fp16(B)[N,K]^T, fp32 accumulate.
// CTA 128x128, 256 threads, 8 warps (4m x 2n), warp tile 32x64.
// K-chunk 64, 3 stages of (A 128x144B + B 128x144B) = 110.6 KB -> 2 CTAs/SM.
// EPI: 1 = +Res -> fp32 C, 2 = exact gelu -> fp16, 3 = QKV + xPos rope -> fp16
#define MM4_PL    18432
#define MM4_STAGE (2*MM4_PL)      // 36864
#define MM4_SMEM  (3*MM4_STAGE)   // 110592

template<int EPI>
__global__ void __launch_bounds__(256, 2) mm4(
    int M, int N, int K,
    const __half* __restrict__ Ah,
    const __half* __restrict__ Bh,
    const float* __restrict__ Res,
    float* __restrict__ Cf,
    __half* __restrict__ Ch,
    __half* __restrict__ qt, __half* __restrict__ kt, __half* __restrict__ vt,
    const int* __restrict__ pidx,
    int tiles_n)
{
    extern __shared__ char smc[];
    const uint32_t smb = hx_smem_u32(smc);
    const int tid  = threadIdx.x;
    const int lane = tid & 31;
    const int warp = tid >> 5;     // 0..7
    const int wm = warp & 3;       // m offset wm*32
    const int wn = warp >> 2;      // n offset wn*64

    // supertile raster: 16 m-tiles per band
    const int SUPER = 16;
    const int per  = SUPER * tiles_n;
    const int band = blockIdx.x / per;
    const int rem  = blockIdx.x % per;
    const int mt  = band * SUPER + (rem % SUPER);
    int ntg = rem / SUPER;

    int sel = 0;
    if (EPI == 3) { sel = ntg >> 4; ntg &= 15; }
    const int nt = ntg;

    const long boff = (EPI == 3) ? (long)sel * 4194304L : 0L;
    const __half* pAh = Ah + (long)mt * 128 * K;
    const __half* pBh = Bh + boff + (long)nt * 128 * K;

    float acc[2][8][4];
#pragma unroll
    for (int i = 0; i < 2; i++)
#pragma unroll
        for (int j = 0; j < 8; j++)
#pragma unroll
            for (int r = 0; r < 4; r++) acc[i][j][r] = 0.f;

    auto issue_chunk = [&](int c, int st) {
        const uint32_t sb = smb + st * MM4_STAGE;
#pragma unroll
        for (int q = 0; q < 8; q++) {
            const int op = tid + q * 256;        // 0..2047
            const int pl = op >> 10;             // 0=A, 1=B
            const int rm = op & 1023;
            const int r  = rm >> 3;              // 0..127
            const int s  = rm & 7;
            const __half* src = (pl ? pBh : pAh) + (long)r * K + c * 64 + s * 8;
            HX_CPASYNC16(sb + pl * MM4_PL + r * 144 + s * 16, src);
        }
        HX_CPCOMMIT();
    };

    const int nch = K / 64;
    issue_chunk(0, 0);
    issue_chunk(1, 1);

    for (int c = 0; c < nch; c++) {
        const int st = c % 3;
        if (c + 1 < nch) { asm volatile("cp.async.wait_group 1;" ::: "memory"); }
        else             { asm volatile("cp.async.wait_group 0;" ::: "memory"); }
        __syncthreads();
        if (c + 2 < nch) issue_chunk(c + 2, (c + 2) % 3);

        const uint32_t stb = smb + st * MM4_STAGE;
#pragma unroll
        for (int ks = 0; ks < 4; ks++) {
            const uint32_t colb = ks * 32 + (lane >> 4) * 16;
            uint32_t ah[2][4], bh[4][4];
#pragma unroll
            for (int im = 0; im < 2; im++) {
                const uint32_t row = wm * 32 + im * 16 + (lane & 15);
                HX_LDSM4(ah[im], stb + row * 144 + colb);
            }
#pragma unroll
            for (int ib = 0; ib < 4; ib++) {
                const uint32_t row = wn * 64 + ib * 16 + (lane & 15);
                HX_LDSM4(bh[ib], stb + MM4_PL + row * 144 + colb);
            }
#pragma unroll
            for (int im = 0; im < 2; im++)
#pragma unroll
                for (int j = 0; j < 8; j++)
                    HX_MMA(acc[im][j], ah[im], bh[j>>1][j&1], bh[j>>1][(j&1)+2]);
        }
    }

    // ---- epilogue ----
    const int pos = (EPI == 3) ? pidx[0] : 0;
#pragma unroll
    for (int im = 0; im < 2; im++)
#pragma unroll
        for (int j = 0; j < 8; j++) {
            const long row0 = (long)mt * 128 + wm * 32 + im * 16 + (lane >> 2);
            const long col  = (long)nt * 128 + wn * 64 + j * 8 + (lane & 3) * 2;
            float2 v0 = { acc[im][j][0], acc[im][j][1] };   // row0,   (col, col+1)
            float2 v1 = { acc[im][j][2], acc[im][j][3] };   // row0+8, (col, col+1)
            if (EPI == 3) {
                const int h = (int)(col >> 7);
                const int d = (int)(col & 127);
                const int s0 = (int)(row0 & 1023), b0 = (int)(row0 >> 10);
                const int s1 = (int)((row0 + 8) & 1023), b1 = (int)((row0 + 8) >> 10);
                const long out0 = (((long)(b0*16 + h))*1024 + s0)*128 + d;
                const long out1 = (((long)(b1*16 + h))*1024 + s1)*128 + d;
                __half* dst = (sel == 0) ? qt : (sel == 1) ? kt : vt;
                if (sel == 0) {
                    *(uint32_t*)(dst + out0) = hx_pkf(v0.x, v0.y);
                    *(uint32_t*)(dst + out1) = hx_pkf(v1.x, v1.y);
                } else {
                    const float df    = 2.0f * (float)((d >> 1) + 1);
                    const float theta = __expf(-(df * (1.0f/128.0f)) * 9.210340371976184f);
                    const float lz    = __logf((df*(1.0f/64.0f) + 51.2f) * (1.0f/52.2f));
                    const float seq0 = (float)(pos + s0 - 512) * (1.0f/512.0f);
                    const float seq1 = (float)(pos + s1 - 512) * (1.0f/512.0f);
                    float sn0, cs0, sn1, cs1;
                    __sincosf(seq0*theta, &sn0, &cs0);
                    __sincosf(seq1*theta, &sn1, &cs1);
                    float t0 = __expf(seq0*lz), t1 = __expf(seq1*lz);
                    if (sel == 2) { t0 = 1.0f/t0; t1 = 1.0f/t1; }
                    const float x0 = (v0.x*cs0 - v0.y*sn0)*t0;
                    const float y0 = (v0.y*cs0 + v0.x*sn0)*t0;
                    const float x1 = (v1.x*cs1 - v1.y*sn1)*t1;
                    const float y1 = (v1.y*cs1 + v1.x*sn1)*t1;
                    *(uint32_t*)(dst + out0) = hx_pkf(x0, y0);
                    *(uint32_t*)(dst + out1) = hx_pkf(x1, y1);
                }
            } else {
                const long o0 = row0 * N + col;
                const long o1 = (row0 + 8) * N + col;
                if (EPI == 2) {
                    v0.x = 0.5f*v0.x*(1.0f + erff(v0.x*0.70710678118654752f));
                    v0.y = 0.5f*v0.y*(1.0f + erff(v0.y*0.70710678118654752f));
                    v1.x = 0.5f*v1.x*(1.0f + erff(v1.x*0.70710678118654752f));
                    v1.y = 0.5f*v1.y*(1.0f + erff(v1.y*0.70710678118654752f));
                    *(uint32_t*)(Ch + o0) = hx_pkf(v0.x, v0.y);
                    *(uint32_t*)(Ch + o1) = hx_pkf(v1.x, v1.y);
                } else {
                    const float2 r0 = *(const float2*)(Res + o0);
                    const float2 r1 = *(const float2*)(Res + o1);
                    v0.x += r0.x; v0.y += r0.y; v1.x += r1.x; v1.y += r1.y;
                    *(float2*)(Cf + o0) = v0;
                    *(float2*)(Cf + o1) = v1;
                }
            }
        }
}

// ---------------- LayerNorm -> fp16 plane -----------------------------------
__global__ void __launch_bounds__(256) hx_ln(const float* __restrict__ x,
                                             const float* __restrict__ w,
                                             __half* __restrict__ outh)
{
    const int row = blockIdx.x;
    const int tid = threadIdx.x;
    const float4* xr = (const float4*)(x + (long)row*HID_);
    float4 a = xr[tid];
    float4 b = xr[tid + 256];
    float s  = a.x+a.y+a.z+a.w + b.x+b.y+b.z+b.w;
    float s2 = a.x*a.x+a.y*a.y+a.z*a.z+a.w*a.w
             + b.x*b.x+b.y*b.y+b.z*b.z+b.w*b.w;
#pragma unroll
    for (int o = 16; o; o >>= 1) {
        s  += __shfl_xor_sync(0xffffffffu, s,  o);
        s2 += __shfl_xor_sync(0xffffffffu, s2, o);
    }
    __shared__ float sh[16];
    if ((tid & 31) == 0) { sh[tid >> 5] = s; sh[(tid >> 5) + 8] = s2; }
    __syncthreads();
    float ts = 0.f, ts2 = 0.f;
#pragma unroll
    for (int i = 0; i < 8; i++) { ts += sh[i]; ts2 += sh[i + 8]; }
    const float mean = ts * (1.0f/HID_);
    const float var  = ts2 * (1.0f/HID_) - mean*mean;
    const float rstd = rsqrtf(var + 1e-5f);

    const float4* wr = (const float4*)w;
    float4 w0 = wr[tid], w1v = wr[tid + 256];
    float4 o0, o1;
    o0.x = (a.x-mean)*rstd*w0.x;  o0.y = (a.y-mean)*rstd*w0.y;
    o0.z = (a.z-mean)*rstd*w0.z;  o0.w = (a.w-mean)*rstd*w0.w;
    o1.x = (b.x-mean)*rstd*w1v.x; o1.y = (b.y-mean)*rstd*w1v.y;
    o1.z = (b.z-mean)*rstd*w1v.z; o1.w = (b.w-mean)*rstd*w1v.w;

    *(uint2*)(outh + (long)row*HID_ + tid*4)       = hx_cvt4h(o0);
    *(uint2*)(outh + (long)row*HID_ + (tid+256)*4) = hx_cvt4h(o1);
}

// ---------------- fp16 tensor-core causal flash attention (3-stage) ---------
// Grid: (bh = 128, qb_rev = 8); qb = 7 - blockIdx.y so the LONGEST CTAs
// (most KV tiles) dispatch first -> balanced makespan under causal skew.
#define AT_ROW    272
#define AT_Q      0
#define AT_QBYTES (128*AT_ROW)        // 34816
#define AT_KB     17408               // 64*272
#define AT_STAGE  (2*AT_KB)           // 34816
#define AT_SMEM   (AT_QBYTES + 3*AT_STAGE)  // 139264

__global__ void __launch_bounds__(256, 1) hx_attn16(
    const __half* __restrict__ qt, const __half* __restrict__ kt,
    const __half* __restrict__ vt, __half* __restrict__ ctxh)
{
    extern __shared__ char smc[];
    const uint32_t smb = hx_smem_u32(smc);
    const int tid = threadIdx.x, lane = tid & 31, warp = tid >> 5;
    const int qb = (int)(gridDim.y - 1 - blockIdx.y);   // longest first
    const int bh = blockIdx.x;
    const int b = bh >> 4, h = bh & 15;
    const int wrow = warp * 16;

    const __half* Qg = qt + ((long)bh*S_ + qb*128)*D_;
    const __half* Kg = kt + (long)bh*S_*D_;
    const __half* Vg = vt + (long)bh*S_*D_;

#pragma unroll
    for (int p = 0; p < 8; p++) {
        const int op = tid + p*256;
        const int r = op >> 4, s = op & 15;
        HX_CPASYNC16(smb + AT_Q + r*AT_ROW + s*16, Qg + (long)r*D_ + s*8);
    }
    auto issue_kv = [&](int j, int st) {
        const uint32_t sb = smb + AT_QBYTES + st*AT_STAGE;
#pragma unroll
        for (int p = 0; p < 8; p++) {
            const int op = tid + p*256;
            const int kv = op >> 10;
            const int rm = op & 1023;
            const int r = rm >> 4, s = rm & 15;
            const __half* src = (kv ? Vg : Kg) + (long)(j*64 + r)*D_ + s*8;
            HX_CPASYNC16(sb + kv*AT_KB + r*AT_ROW + s*16, src);
        }
        HX_CPCOMMIT();
    };

    const int njt = 2*qb + 2;
    issue_kv(0, 0);
    issue_kv(1, 1);
    asm volatile("cp.async.wait_group 1;" ::: "memory");
    __syncthreads();

    uint32_t qf[8][4];
#pragma unroll
    for (int kb = 0; kb < 8; kb++)
        HX_LDSM4(qf[kb], smb + AT_Q + (wrow + (lane & 15))*AT_ROW + kb*32 + (lane >> 4)*16);

    float o[16][4];
#pragma unroll
    for (int nd = 0; nd < 16; nd++)
#pragma unroll
        for (int r = 0; r < 4; r++) o[nd][r] = 0.f;
    float mi0 = -INFINITY, mi1 = -INFINITY, li0 = 0.f, li1 = 0.f;

    const float scale = 0.088388347648318447f;
    const int r0g = qb*128 + wrow + (lane >> 2);
    const int c0l = (lane & 3)*2;

    for (int j = 0; j < njt; j++) {
        const int st = j % 3;
        if (j > 0) {
            if (j + 1 < njt) { asm volatile("cp.async.wait_group 1;" ::: "memory"); }
            else             { asm volatile("cp.async.wait_group 0;" ::: "memory"); }
            __syncthreads();
        }
        // prefetch into the 3rd stage BEFORE compute of this stage
        if (j + 2 < njt) issue_kv(j + 2, (j + 2) % 3);

        const uint32_t kb_ = smb + AT_QBYTES + st*AT_STAGE;
        const uint32_t vb_ = kb_ + AT_KB;

        float sacc[8][4];
#pragma unroll
        for (int nb = 0; nb < 8; nb++)
#pragma unroll
            for (int r = 0; r < 4; r++) sacc[nb][r] = 0.f;
#pragma unroll
        for (int ng = 0; ng < 4; ng++) {
#pragma unroll
            for (int kb = 0; kb < 8; kb++) {
                uint32_t kf[4];
                HX_LDSM4(kf, kb_ + (ng*16 + (lane & 15))*AT_ROW + kb*32 + (lane >> 4)*16);
                HX_MMA(sacc[ng*2+0], qf[kb], kf[0], kf[2]);
                HX_MMA(sacc[ng*2+1], qf[kb], kf[1], kf[3]);
            }
        }

        float rmax0 = -INFINITY, rmax1 = -INFINITY;
#pragma unroll
        for (int nb = 0; nb < 8; nb++) {
            const int cg = j*64 + nb*8 + c0l;
            float v0 = sacc[nb][0]*scale; if (cg     > r0g)     v0 = -INFINITY;
            float v1 = sacc[nb][1]*scale; if (cg + 1 > r0g)     v1 = -INFINITY;
            float v2 = sacc[nb][2]*scale; if (cg     > r0g + 8) v2 = -INFINITY;
            float v3 = sacc[nb][3]*scale; if (cg + 1 > r0g + 8) v3 = -INFINITY;
            sacc[nb][0] = v0; sacc[nb][1] = v1; sacc[nb][2] = v2; sacc[nb][3] = v3;
            rmax0 = fmaxf(rmax0, fmaxf(v0, v1));
            rmax1 = fmaxf(rmax1, fmaxf(v2, v3));
        }
        rmax0 = fmaxf(rmax0, __shfl_xor_sync(0xffffffffu, rmax0, 1));
        rmax0 = fmaxf(rmax0, __shfl_xor_sync(0xffffffffu, rmax0, 2));
        rmax1 = fmaxf(rmax1, __shfl_xor_sync(0xffffffffu, rmax1, 1));
        rmax1 = fmaxf(rmax1, __shfl_xor_sync(0xffffffffu, rmax1, 2));
        const float mn0 = fmaxf(mi0, rmax0), mn1 = fmaxf(mi1, rmax1);
        const float a0 = __expf(mi0 - mn0), a1 = __expf(mi1 - mn1);
        float rs0 = 0.f, rs1 = 0.f;
#pragma unroll
        for (int nb = 0; nb < 8; nb++) {
            const float p0 = __expf(sacc[nb][0] - mn0);
            const float p1 = __expf(sacc[nb][1] - mn0);
            const float p2 = __expf(sacc[nb][2] - mn1);
            const float p3 = __expf(sacc[nb][3] - mn1);
            sacc[nb][0] = p0; sacc[nb][1] = p1; sacc[nb][2] = p2; sacc[nb][3] = p3;
            rs0 += p0 + p1; rs1 += p2 + p3;
        }
        rs0 += __shfl_xor_sync(0xffffffffu, rs0, 1);
        rs0 += __shfl_xor_sync(0xffffffffu, rs0, 2);
        rs1 += __shfl_xor_sync(0xffffffffu, rs1, 1);
        rs1 += __shfl_xor_sync(0xffffffffu, rs1, 2);
        li0 = li0*a0 + rs0; li1 = li1*a1 + rs1;
        mi0 = mn0; mi1 = mn1;
#pragma unroll
        for (int nd = 0; nd < 16; nd++) {
            o[nd][0] *= a0; o[nd][1] *= a0; o[nd][2] *= a1; o[nd][3] *= a1;
        }

        uint32_t pa[4][4];
#pragma unroll
        for (int kk = 0; kk < 4; kk++) {
            pa[kk][0] = hx_pkf(sacc[2*kk][0],   sacc[2*kk][1]);
            pa[kk][1] = hx_pkf(sacc[2*kk][2],   sacc[2*kk][3]);
            pa[kk][2] = hx_pkf(sacc[2*kk+1][0], sacc[2*kk+1][1]);
            pa[kk][3] = hx_pkf(sacc[2*kk+1][2], sacc[2*kk+1][3]);
        }

#pragma unroll
        for (int ndg = 0; ndg < 8; ndg++) {
#pragma unroll
            for (int kk = 0; kk < 4; kk++) {
                uint32_t vf[4];
                HX_LDSM4T(vf, vb_ + (kk*16 + (lane & 15))*AT_ROW + ndg*32 + (lane >> 4)*16);
                HX_MMA(o[ndg*2+0], pa[kk], vf[0], vf[1]);
                HX_MMA(o[ndg*2+1], pa[kk], vf[2], vf[3]);
            }
        }
    }

    const float i0 = 1.f/li0, i1 = 1.f/li1;
    const long s0 = (long)(b*S_) + qb*128 + wrow + (lane >> 2);
    const long base0 = s0*HID_ + h*128 + c0l;
    const long base1 = (s0 + 8)*HID_ + h*128 + c0l;
#pragma unroll
    for (int nd = 0; nd < 16; nd++) {
        *(uint32_t*)(ctxh + base0 + nd*8) = hx_pkf(o[nd][0]*i0, o[nd][1]*i0);
        *(uint32_t*)(ctxh + base1 + nd*8) = hx_pkf(o[nd][2]*i1, o[nd][3]*i1);
    }
}

// ---------------- launch ----------------------------------------------------
extern "C" void kernel_launch(void* const* d_in, const int* in_sizes, int n_in,
                              void* d_out, int out_size)
{
    const float* acts_in = (const float*)d_in[0];
    const float* ln1_w   = (const float*)d_in[4];
    const float* ln2_w   = (const float*)d_in[5];
    const float* q_w     = (const float*)d_in[6];
    const float* k_w     = (const float*)d_in[7];
    const float* v_w     = (const float*)d_in[8];
    const float* o_w     = (const float*)d_in[9];
    const float* w1      = (const float*)d_in[10];
    const float* w2      = (const float*)d_in[11];
    const int*   p_index = (const int*)d_in[3];
    float* out = (float*)d_out;

    float *p_acts;
    __half *p_qt, *p_kt, *p_vt, *p_wh, *p_xnh, *p_ctxh, *p_hh;
    cudaGetSymbolAddress((void**)&p_acts, g_acts);
    cudaGetSymbolAddress((void**)&p_qt,   g_qt);
    cudaGetSymbolAddress((void**)&p_kt,   g_kt);
    cudaGetSymbolAddress((void**)&p_vt,   g_vt);
    cudaGetSymbolAddress((void**)&p_wh,   g_wh);
    cudaGetSymbolAddress((void**)&p_xnh,  g_xnh);
    cudaGetSymbolAddress((void**)&p_ctxh, g_ctxh);
    cudaGetSymbolAddress((void**)&p_hh,   g_hh);

    cudaFuncSetAttribute(mm4<1>, cudaFuncAttributeMaxDynamicSharedMemorySize, MM4_SMEM);
    cudaFuncSetAttribute(mm4<2>, cudaFuncAttributeMaxDynamicSharedMemorySize, MM4_SMEM);
    cudaFuncSetAttribute(mm4<3>, cudaFuncAttributeMaxDynamicSharedMemorySize, MM4_SMEM);
    cudaFuncSetAttribute(hx_attn16, cudaFuncAttributeMaxDynamicSharedMemorySize, AT_SMEM);

    // 0) weight fp16 conversion
    hx_wsplit<<<4096, 256>>>(q_w, k_w, v_w, o_w, w1, w2, p_wh);

    // 1) LN1 -> xn fp16
    hx_ln<<<M_, 256>>>(acts_in, ln1_w, p_xnh);

    // 2) fused QKV projection + xPos rope + transpose -> fp16 qt/kt/vt
    mm4<3><<<64*48, 256, MM4_SMEM>>>(M_, HID_, HID_,
        p_xnh, p_wh, nullptr, nullptr, nullptr,
        p_qt, p_kt, p_vt, p_index, 48);

    // 3) fp16 tensor-core causal flash attention -> ctx fp16 (longest-first)
    hx_attn16<<<dim3(B_*H_, S_/128), 256, AT_SMEM>>>(p_qt, p_kt, p_vt, p_ctxh);

    // 4) O projection + residual -> acts fp32
    mm4<1><<<64*16, 256, MM4_SMEM>>>(M_, HID_, HID_,
        p_ctxh, p_wh + OFF_O, acts_in, p_acts, nullptr,
        nullptr, nullptr, nullptr, nullptr, 16);

    // 5) LN2 -> xn fp16 (reuse)
    hx_ln<<<M_, 256>>>(p_acts, ln2_w, p_xnh);

    // 6) FFN up + exact GELU -> h fp16
    mm4<2><<<64*64, 256, MM4_SMEM>>>(M_, FF_, HID_,
        p_xnh, p_wh + OFF_W1, nullptr, nullptr, p_hh,
        nullptr, nullptr, nullptr, nullptr, 64);

    // 7) FFN down + residual -> output acts
    mm4<1><<<64*16, 256, MM4_SMEM>>>(M_, HID_, FF_,
        p_hh, p_wh + OFF_W2, p_acts, out, nullptr,
        nullptr, nullptr, nullptr, nullptr, 16);

    // 8) pass-through caches
    const long actN = (long)M_*HID_;
    if (n_in > 2 && (long)out_size >= actN + (long)in_sizes[1] + (long)in_sizes[2]) {
        cudaMemcpyAsync(out + actN, d_in[1],
                        (size_t)in_sizes[1]*sizeof(float),
                        cudaMemcpyDeviceToDevice);
        cudaMemcpyAsync(out + actN + in_sizes[1], d_in[2],
                        (size_t)in_sizes[2]*sizeof(float),
                        cudaMemcpyDeviceToDevice);
    }
}

// round 17
// speedup vs baseline: 1.0340x; 1.0025x over previous
#include <cuda_runtime.h>
#include <cuda_fp16.h>
#include <cstdint>
#include <math.h>

// ---------------- problem constants ----------------
#define B_    8
#define S_    1024
#define HID_  2048
#define H_    16
#define D_    128
#define M_    (B_*S_)      // 8192 token rows
#define FF_   (4*HID_)     // 8192

// weight plane offsets (elements)
#define OFF_Q   0L
#define OFF_K   4194304L
#define OFF_V   8388608L
#define OFF_O   12582912L
#define OFF_W1  16777216L
#define OFF_W2  33554432L
#define W_TOTAL 50331648L

// ---------------- scratch (device globals; no allocations allowed) --------
__device__ float g_acts[(size_t)M_*HID_];
__device__ __half g_qt  [(size_t)M_*HID_];  // [B*H][S][D] fp16
__device__ __half g_kt  [(size_t)M_*HID_];
__device__ __half g_vt  [(size_t)M_*HID_];
__device__ __half g_wh  [W_TOTAL];          // fp16 weights
__device__ __half g_xnh [(size_t)M_*HID_];  // fp16 activations
__device__ __half g_ctxh[(size_t)M_*HID_];
__device__ __half g_hh  [(size_t)M_*FF_];

// ---------------- helpers ---------------------------------------------------
__device__ __forceinline__ uint32_t hx_smem_u32(const void* p) {
    uint32_t a;
    asm("{ .reg .u64 t; cvta.to.shared.u64 t, %1; cvt.u32.u64 %0, t; }" : "=r"(a) : "l"(p));
    return a;
}
#define HX_LDSM4(r, addr) \
    asm volatile("ldmatrix.sync.aligned.m8n8.x4.shared.b16 {%0,%1,%2,%3}, [%4];" \
        : "=r"((r)[0]), "=r"((r)[1]), "=r"((r)[2]), "=r"((r)[3]) : "r"(addr))
#define HX_LDSM4T(r, addr) \
    asm volatile("ldmatrix.sync.aligned.m8n8.x4.trans.shared.b16 {%0,%1,%2,%3}, [%4];" \
        : "=r"((r)[0]), "=r"((r)[1]), "=r"((r)[2]), "=r"((r)[3]) : "r"(addr))

#define HX_MMA(d, a, b0, b1) \
    asm volatile("mma.sync.aligned.m16n8k16.row.col.f32.f16.f16.f32 " \
        "{%0,%1,%2,%3}, {%4,%5,%6,%7}, {%8,%9}, {%0,%1,%2,%3};" \
        : "+f"((d)[0]), "+f"((d)[1]), "+f"((d)[2]), "+f"((d)[3]) \
        : "r"((a)[0]), "r"((a)[1]), "r"((a)[2]), "r"((a)[3]), "r"(b0), "r"(b1))

#define HX_CPASYNC16(dst, src) \
    asm volatile("cp.async.cg.shared.global [%0], [%1], 16;" :: "r"(dst), "l"(src) : "memory")
#define HX_CPCOMMIT() asm volatile("cp.async.commit_group;" ::: "memory")

__device__ __forceinline__ uint32_t hx_pkh(__half a, __half b) {
    __half2 t; t.x = a; t.y = b;
    return *(uint32_t*)&t;
}
// pack (lo=a, hi=b) with one cvt.rn.f16x2.f32 (first src -> hi, second -> lo)
__device__ __forceinline__ uint32_t hx_pkf(float a, float b) {
    uint32_t r;
    asm("cvt.rn.f16x2.f32 %0, %1, %2;" : "=r"(r) : "f"(b), "f"(a));
    return r;
}
__device__ __forceinline__ uint2 hx_cvt4h(float4 v) {
    uint2 h;
    h.x = hx_pkf(v.x, v.y);
    h.y = hx_pkf(v.z, v.w);
    return h;
}

// ---------------- weight fp16 conversion ------------------------------------
__global__ void __launch_bounds__(256) hx_wsplit(
    const float* __restrict__ qw, const float* __restrict__ kw,
    const float* __restrict__ vw, const float* __restrict__ ow,
    const float* __restrict__ w1, const float* __restrict__ w2,
    __half* __restrict__ wh)
{
    const long stride = (long)gridDim.x * blockDim.x;
    for (long i = (long)blockIdx.x * blockDim.x + threadIdx.x;
         i * 4 < W_TOTAL; i += stride) {
        const long e = i * 4;
        const float* src; long off;
        if (e < OFF_W1) {
            const int m = (int)(e >> 22);
            src = (m == 0) ? qw : (m == 1) ? kw : (m == 2) ? vw : ow;
            off = e & 4194303L;
        } else if (e < OFF_W2) { src = w1; off = e - OFF_W1; }
        else                   { src = w2; off = e - OFF_W2; }
        float4 v = *(const float4*)(src + off);
        *(uint2*)(wh + e) = hx_cvt4h(v);
    }
}

// ---------------- fp16 tensor-core GEMM v8 (2 CTAs/SM) ----------------------
// C[M,N] = fp16(A)[M,K] @ fp16(B)[N,K]^T, fp32 accumulate.
// CTA 128x128, 256 threads, 8 warps (4m x 2n), warp tile 32x64.
// K-chunk 64, 3 stages of (A 128x144B + B 128x144B) = 110.6 KB -> 2 CTAs/SM.
// EPI: 1 = +Res -> fp32 C, 2 = exact gelu -> fp16, 3 = QKV + xPos rope -> fp16
#define MM4_PL    18432
#define MM4_STAGE (2*MM4_PL)      // 36864
#define MM4_SMEM  (3*MM4_STAGE)   // 110592

template<int EPI>
__global__ void __launch_bounds__(256, 2) mm4(
    int M, int N, int K,
    const __half* __restrict__ Ah,
    const __half* __restrict__ Bh,
    const float* __restrict__ Res,
    float* __restrict__ Cf,
    __half* __restrict__ Ch,
    __half* __restrict__ qt, __half* __restrict__ kt, __half* __restrict__ vt,
    const int* __restrict__ pidx,
    int tiles_n)
{
    extern __shared__ char smc[];
    const uint32_t smb = hx_smem_u32(smc);
    const int tid  = threadIdx.x;
    const int lane = tid & 31;
    const int warp = tid >> 5;     // 0..7
    const int wm = warp & 3;       // m offset wm*32
    const int wn = warp >> 2;      // n offset wn*64

    // supertile raster: 16 m-tiles per band
    const int SUPER = 16;
    const int per  = SUPER * tiles_n;
    const int band = blockIdx.x / per;
    const int rem  = blockIdx.x % per;
    const int mt  = band * SUPER + (rem % SUPER);
    int ntg = rem / SUPER;

    int sel = 0;
    if (EPI == 3) { sel = ntg >> 4; ntg &= 15; }
    const int nt = ntg;

    const long boff = (EPI == 3) ? (long)sel * 4194304L : 0L;
    const __half* pAh = Ah + (long)mt * 128 * K;
    const __half* pBh = Bh + boff + (long)nt * 128 * K;

    float acc[2][8][4];
#pragma unroll
    for (int i = 0; i < 2; i++)
#pragma unroll
        for (int j = 0; j < 8; j++)
#pragma unroll
            for (int r = 0; r < 4; r++) acc[i][j][r] = 0.f;

    auto issue_chunk = [&](int c, int st) {
        const uint32_t sb = smb + st * MM4_STAGE;
#pragma unroll
        for (int q = 0; q < 8; q++) {
            const int op = tid + q * 256;        // 0..2047
            const int pl = op >> 10;             // 0=A, 1=B
            const int rm = op & 1023;
            const int r  = rm >> 3;              // 0..127
            const int s  = rm & 7;
            const __half* src = (pl ? pBh : pAh) + (long)r * K + c * 64 + s * 8;
            HX_CPASYNC16(sb + pl * MM4_PL + r * 144 + s * 16, src);
        }
        HX_CPCOMMIT();
    };

    const int nch = K / 64;
    issue_chunk(0, 0);
    issue_chunk(1, 1);

    for (int c = 0; c < nch; c++) {
        const int st = c % 3;
        if (c + 1 < nch) { asm volatile("cp.async.wait_group 1;" ::: "memory"); }
        else             { asm volatile("cp.async.wait_group 0;" ::: "memory"); }
        __syncthreads();
        if (c + 2 < nch) issue_chunk(c + 2, (c + 2) % 3);

        const uint32_t stb = smb + st * MM4_STAGE;
#pragma unroll
        for (int ks = 0; ks < 4; ks++) {
            const uint32_t colb = ks * 32 + (lane >> 4) * 16;
            uint32_t ah[2][4], bh[4][4];
#pragma unroll
            for (int im = 0; im < 2; im++) {
                const uint32_t row = wm * 32 + im * 16 + (lane & 15);
                HX_LDSM4(ah[im], stb + row * 144 + colb);
            }
#pragma unroll
            for (int ib = 0; ib < 4; ib++) {
                const uint32_t row = wn * 64 + ib * 16 + (lane & 15);
                HX_LDSM4(bh[ib], stb + MM4_PL + row * 144 + colb);
            }
#pragma unroll
            for (int im = 0; im < 2; im++)
#pragma unroll
                for (int j = 0; j < 8; j++)
                    HX_MMA(acc[im][j], ah[im], bh[j>>1][j&1], bh[j>>1][(j&1)+2]);
        }
    }

    // ---- epilogue ----
    const int pos = (EPI == 3) ? pidx[0] : 0;
#pragma unroll
    for (int im = 0; im < 2; im++)
#pragma unroll
        for (int j = 0; j < 8; j++) {
            const long row0 = (long)mt * 128 + wm * 32 + im * 16 + (lane >> 2);
            const long col  = (long)nt * 128 + wn * 64 + j * 8 + (lane & 3) * 2;
            float2 v0 = { acc[im][j][0], acc[im][j][1] };   // row0,   (col, col+1)
            float2 v1 = { acc[im][j][2], acc[im][j][3] };   // row0+8, (col, col+1)
            if (EPI == 3) {
                const int h = (int)(col >> 7);
                const int d = (int)(col & 127);
                const int s0 = (int)(row0 & 1023), b0 = (int)(row0 >> 10);
                const int s1 = (int)((row0 + 8) & 1023), b1 = (int)((row0 + 8) >> 10);
                const long out0 = (((long)(b0*16 + h))*1024 + s0)*128 + d;
                const long out1 = (((long)(b1*16 + h))*1024 + s1)*128 + d;
                __half* dst = (sel == 0) ? qt : (sel == 1) ? kt : vt;
                if (sel == 0) {
                    *(uint32_t*)(dst + out0) = hx_pkf(v0.x, v0.y);
                    *(uint32_t*)(dst + out1) = hx_pkf(v1.x, v1.y);
                } else {
                    const float df    = 2.0f * (float)((d >> 1) + 1);
                    const float theta = __expf(-(df * (1.0f/128.0f)) * 9.210340371976184f);
                    const float lz    = __logf((df*(1.0f/64.0f) + 51.2f) * (1.0f/52.2f));
                    const float seq0 = (float)(pos + s0 - 512) * (1.0f/512.0f);
                    const float seq1 = (float)(pos + s1 - 512) * (1.0f/512.0f);
                    float sn0, cs0, sn1, cs1;
                    __sincosf(seq0*theta, &sn0, &cs0);
                    __sincosf(seq1*theta, &sn1, &cs1);
                    float t0 = __expf(seq0*lz), t1 = __expf(seq1*lz);
                    if (sel == 2) { t0 = 1.0f/t0; t1 = 1.0f/t1; }
                    const float x0 = (v0.x*cs0 - v0.y*sn0)*t0;
                    const float y0 = (v0.y*cs0 + v0.x*sn0)*t0;
                    const float x1 = (v1.x*cs1 - v1.y*sn1)*t1;
                    const float y1 = (v1.y*cs1 + v1.x*sn1)*t1;
                    *(uint32_t*)(dst + out0) = hx_pkf(x0, y0);
                    *(uint32_t*)(dst + out1) = hx_pkf(x1, y1);
                }
            } else {
                const long o0 = row0 * N + col;
                const long o1 = (row0 + 8) * N + col;
                if (EPI == 2) {
                    v0.x = 0.5f*v0.x*(1.0f + erff(v0.x*0.70710678118654752f));
                    v0.y = 0.5f*v0.y*(1.0f + erff(v0.y*0.70710678118654752f));
                    v1.x = 0.5f*v1.x*(1.0f + erff(v1.x*0.70710678118654752f));
                    v1.y = 0.5f*v1.y*(1.0f + erff(v1.y*0.70710678118654752f));
                    *(uint32_t*)(Ch + o0) = hx_pkf(v0.x, v0.y);
                    *(uint32_t*)(Ch + o1) = hx_pkf(v1.x, v1.y);
                } else {
                    const float2 r0 = *(const float2*)(Res + o0);
                    const float2 r1 = *(const float2*)(Res + o1);
                    v0.x += r0.x; v0.y += r0.y; v1.x += r1.x; v1.y += r1.y;
                    *(float2*)(Cf + o0) = v0;
                    *(float2*)(Cf + o1) = v1;
                }
            }
        }
}

// ---------------- LayerNorm -> fp16 plane -----------------------------------
__global__ void __launch_bounds__(256) hx_ln(const float* __restrict__ x,
                                             const float* __restrict__ w,
                                             __half* __restrict__ outh)
{
    const int row = blockIdx.x;
    const int tid = threadIdx.x;
    const float4* xr = (const float4*)(x + (long)row*HID_);
    float4 a = xr[tid];
    float4 b = xr[tid + 256];
    float s  = a.x+a.y+a.z+a.w + b.x+b.y+b.z+b.w;
    float s2 = a.x*a.x+a.y*a.y+a.z*a.z+a.w*a.w
             + b.x*b.x+b.y*b.y+b.z*b.z+b.w*b.w;
#pragma unroll
    for (int o = 16; o; o >>= 1) {
        s  += __shfl_xor_sync(0xffffffffu, s,  o);
        s2 += __shfl_xor_sync(0xffffffffu, s2, o);
    }
    __shared__ float sh[16];
    if ((tid & 31) == 0) { sh[tid >> 5] = s; sh[(tid >> 5) + 8] = s2; }
    __syncthreads();
    float ts = 0.f, ts2 = 0.f;
#pragma unroll
    for (int i = 0; i < 8; i++) { ts += sh[i]; ts2 += sh[i + 8]; }
    const float mean = ts * (1.0f/HID_);
    const float var  = ts2 * (1.0f/HID_) - mean*mean;
    const float rstd = rsqrtf(var + 1e-5f);

    const float4* wr = (const float4*)w;
    float4 w0 = wr[tid], w1v = wr[tid + 256];
    float4 o0, o1;
    o0.x = (a.x-mean)*rstd*w0.x;  o0.y = (a.y-mean)*rstd*w0.y;
    o0.z = (a.z-mean)*rstd*w0.z;  o0.w = (a.w-mean)*rstd*w0.w;
    o1.x = (b.x-mean)*rstd*w1v.x; o1.y = (b.y-mean)*rstd*w1v.y;
    o1.z = (b.z-mean)*rstd*w1v.z; o1.w = (b.w-mean)*rstd*w1v.w;

    *(uint2*)(outh + (long)row*HID_ + tid*4)       = hx_cvt4h(o0);
    *(uint2*)(outh + (long)row*HID_ + (tid+256)*4) = hx_cvt4h(o1);
}

// ---------------- fp16 tensor-core causal flash attention (3-stage) ---------
// Grid: (bh = 128, qb_rev = 8); qb = 7 - blockIdx.y (longest CTAs first).
// Diagonal-only masking: tiles fully below the causal frontier skip predicates.
#define AT_ROW    272
#define AT_Q      0
#define AT_QBYTES (128*AT_ROW)        // 34816
#define AT_KB     17408               // 64*272
#define AT_STAGE  (2*AT_KB)           // 34816
#define AT_SMEM   (AT_QBYTES + 3*AT_STAGE)  // 139264

__global__ void __launch_bounds__(256, 1) hx_attn16(
    const __half* __restrict__ qt, const __half* __restrict__ kt,
    const __half* __restrict__ vt, __half* __restrict__ ctxh)
{
    extern __shared__ char smc[];
    const uint32_t smb = hx_smem_u32(smc);
    const int tid = threadIdx.x, lane = tid & 31, warp = tid >> 5;
    const int qb = (int)(gridDim.y - 1 - blockIdx.y);   // longest first
    const int bh = blockIdx.x;
    const int b = bh >> 4, h = bh & 15;
    const int wrow = warp * 16;

    const __half* Qg = qt + ((long)bh*S_ + qb*128)*D_;
    const __half* Kg = kt + (long)bh*S_*D_;
    const __half* Vg = vt + (long)bh*S_*D_;

#pragma unroll
    for (int p = 0; p < 8; p++) {
        const int op = tid + p*256;
        const int r = op >> 4, s = op & 15;
        HX_CPASYNC16(smb + AT_Q + r*AT_ROW + s*16, Qg + (long)r*D_ + s*8);
    }
    auto issue_kv = [&](int j, int st) {
        const uint32_t sb = smb + AT_QBYTES + st*AT_STAGE;
#pragma unroll
        for (int p = 0; p < 8; p++) {
            const int op = tid + p*256;
            const int kv = op >> 10;
            const int rm = op & 1023;
            const int r = rm >> 4, s = rm & 15;
            const __half* src = (kv ? Vg : Kg) + (long)(j*64 + r)*D_ + s*8;
            HX_CPASYNC16(sb + kv*AT_KB + r*AT_ROW + s*16, src);
        }
        HX_CPCOMMIT();
    };

    const int njt = 2*qb + 2;
    issue_kv(0, 0);
    issue_kv(1, 1);
    asm volatile("cp.async.wait_group 1;" ::: "memory");
    __syncthreads();

    uint32_t qf[8][4];
#pragma unroll
    for (int kb = 0; kb < 8; kb++)
        HX_LDSM4(qf[kb], smb + AT_Q + (wrow + (lane & 15))*AT_ROW + kb*32 + (lane >> 4)*16);

    float o[16][4];
#pragma unroll
    for (int nd = 0; nd < 16; nd++)
#pragma unroll
        for (int r = 0; r < 4; r++) o[nd][r] = 0.f;
    float mi0 = -INFINITY, mi1 = -INFINITY, li0 = 0.f, li1 = 0.f;

    const float scale = 0.088388347648318447f;
    const int r0g = qb*128 + wrow + (lane >> 2);
    const int wminrow = qb*128 + wrow;          // warp-uniform min row
    const int c0l = (lane & 3)*2;

    for (int j = 0; j < njt; j++) {
        const int st = j % 3;
        if (j > 0) {
            if (j + 1 < njt) { asm volatile("cp.async.wait_group 1;" ::: "memory"); }
            else             { asm volatile("cp.async.wait_group 0;" ::: "memory"); }
            __syncthreads();
        }
        // prefetch into the 3rd stage BEFORE compute of this stage
        if (j + 2 < njt) issue_kv(j + 2, (j + 2) % 3);

        const uint32_t kb_ = smb + AT_QBYTES + st*AT_STAGE;
        const uint32_t vb_ = kb_ + AT_KB;

        float sacc[8][4];
#pragma unroll
        for (int nb = 0; nb < 8; nb++)
#pragma unroll
            for (int r = 0; r < 4; r++) sacc[nb][r] = 0.f;
#pragma unroll
        for (int ng = 0; ng < 4; ng++) {
#pragma unroll
            for (int kb = 0; kb < 8; kb++) {
                uint32_t kf[4];
                HX_LDSM4(kf, kb_ + (ng*16 + (lane & 15))*AT_ROW + kb*32 + (lane >> 4)*16);
                HX_MMA(sacc[ng*2+0], qf[kb], kf[0], kf[2]);
                HX_MMA(sacc[ng*2+1], qf[kb], kf[1], kf[3]);
            }
        }

        float rmax0 = -INFINITY, rmax1 = -INFINITY;
        if (j*64 + 63 <= wminrow) {
            // fully unmasked tile (warp-uniform): scale only
#pragma unroll
            for (int nb = 0; nb < 8; nb++) {
                const float v0 = sacc[nb][0]*scale;
                const float v1 = sacc[nb][1]*scale;
                const float v2 = sacc[nb][2]*scale;
                const float v3 = sacc[nb][3]*scale;
                sacc[nb][0] = v0; sacc[nb][1] = v1; sacc[nb][2] = v2; sacc[nb][3] = v3;
                rmax0 = fmaxf(rmax0, fmaxf(v0, v1));
                rmax1 = fmaxf(rmax1, fmaxf(v2, v3));
            }
        } else {
#pragma unroll
            for (int nb = 0; nb < 8; nb++) {
                const int cg = j*64 + nb*8 + c0l;
                float v0 = sacc[nb][0]*scale; if (cg     > r0g)     v0 = -INFINITY;
                float v1 = sacc[nb][1]*scale; if (cg + 1 > r0g)     v1 = -INFINITY;
                float v2 = sacc[nb][2]*scale; if (cg     > r0g + 8) v2 = -INFINITY;
                float v3 = sacc[nb][3]*scale; if (cg + 1 > r0g + 8) v3 = -INFINITY;
                sacc[nb][0] = v0; sacc[nb][1] = v1; sacc[nb][2] = v2; sacc[nb][3] = v3;
                rmax0 = fmaxf(rmax0, fmaxf(v0, v1));
                rmax1 = fmaxf(rmax1, fmaxf(v2, v3));
            }
        }
        rmax0 = fmaxf(rmax0, __shfl_xor_sync(0xffffffffu, rmax0, 1));
        rmax0 = fmaxf(rmax0, __shfl_xor_sync(0xffffffffu, rmax0, 2));
        rmax1 = fmaxf(rmax1, __shfl_xor_sync(0xffffffffu, rmax1, 1));
        rmax1 = fmaxf(rmax1, __shfl_xor_sync(0xffffffffu, rmax1, 2));
        const float mn0 = fmaxf(mi0, rmax0), mn1 = fmaxf(mi1, rmax1);
        const float a0 = __expf(mi0 - mn0), a1 = __expf(mi1 - mn1);
        float rs0 = 0.f, rs1 = 0.f;
#pragma unroll
        for (int nb = 0; nb < 8; nb++) {
            const float p0 = __expf(sacc[nb][0] - mn0);
            const float p1 = __expf(sacc[nb][1] - mn0);
            const float p2 = __expf(sacc[nb][2] - mn1);
            const float p3 = __expf(sacc[nb][3] - mn1);
            sacc[nb][0] = p0; sacc[nb][1] = p1; sacc[nb][2] = p2; sacc[nb][3] = p3;
            rs0 += p0 + p1; rs1 += p2 + p3;
        }
        rs0 += __shfl_xor_sync(0xffffffffu, rs0, 1);
        rs0 += __shfl_xor_sync(0xffffffffu, rs0, 2);
        rs1 += __shfl_xor_sync(0xffffffffu, rs1, 1);
        rs1 += __shfl_xor_sync(0xffffffffu, rs1, 2);
        li0 = li0*a0 + rs0; li1 = li1*a1 + rs1;
        mi0 = mn0; mi1 = mn1;
#pragma unroll
        for (int nd = 0; nd < 16; nd++) {
            o[nd][0] *= a0; o[nd][1] *= a0; o[nd][2] *= a1; o[nd][3] *= a1;
        }

        uint32_t pa[4][4];
#pragma unroll
        for (int kk = 0; kk < 4; kk++) {
            pa[kk][0] = hx_pkf(sacc[2*kk][0],   sacc[2*kk][1]);
            pa[kk][1] = hx_pkf(sacc[2*kk][2],   sacc[2*kk][3]);
            pa[kk][2] = hx_pkf(sacc[2*kk+1][0], sacc[2*kk+1][1]);
            pa[kk][3] = hx_pkf(sacc[2*kk+1][2], sacc[2*kk+1][3]);
        }

#pragma unroll
        for (int ndg = 0; ndg < 8; ndg++) {
#pragma unroll
            for (int kk = 0; kk < 4; kk++) {
                uint32_t vf[4];
                HX_LDSM4T(vf, vb_ + (kk*16 + (lane & 15))*AT_ROW + ndg*32 + (lane >> 4)*16);
                HX_MMA(o[ndg*2+0], pa[kk], vf[0], vf[1]);
                HX_MMA(o[ndg*2+1], pa[kk], vf[2], vf[3]);
            }
        }
    }

    const float i0 = 1.f/li0, i1 = 1.f/li1;
    const long s0 = (long)(b*S_) + qb*128 + wrow + (lane >> 2);
    const long base0 = s0*HID_ + h*128 + c0l;
    const long base1 = (s0 + 8)*HID_ + h*128 + c0l;
#pragma unroll
    for (int nd = 0; nd < 16; nd++) {
        *(uint32_t*)(ctxh + base0 + nd*8) = hx_pkf(o[nd][0]*i0, o[nd][1]*i0);
        *(uint32_t*)(ctxh + base1 + nd*8) = hx_pkf(o[nd][2]*i1, o[nd][3]*i1);
    }
}

// ---------------- launch ----------------------------------------------------
extern "C" void kernel_launch(void* const* d_in, const int* in_sizes, int n_in,
                              void* d_out, int out_size)
{
    const float* acts_in = (const float*)d_in[0];
    const float* ln1_w   = (const float*)d_in[4];
    const float* ln2_w   = (const float*)d_in[5];
    const float* q_w     = (const float*)d_in[6];
    const float* k_w     = (const float*)d_in[7];
    const float* v_w     = (const float*)d_in[8];
    const float* o_w     = (const float*)d_in[9];
    const float* w1      = (const float*)d_in[10];
    const float* w2      = (const float*)d_in[11];
    const int*   p_index = (const int*)d_in[3];
    float* out = (float*)d_out;

    float *p_acts;
    __half *p_qt, *p_kt, *p_vt, *p_wh, *p_xnh, *p_ctxh, *p_hh;
    cudaGetSymbolAddress((void**)&p_acts, g_acts);
    cudaGetSymbolAddress((void**)&p_qt,   g_qt);
    cudaGetSymbolAddress((void**)&p_kt,   g_kt);
    cudaGetSymbolAddress((void**)&p_vt,   g_vt);
    cudaGetSymbolAddress((void**)&p_wh,   g_wh);
    cudaGetSymbolAddress((void**)&p_xnh,  g_xnh);
    cudaGetSymbolAddress((void**)&p_ctxh, g_ctxh);
    cudaGetSymbolAddress((void**)&p_hh,   g_hh);

    cudaFuncSetAttribute(mm4<1>, cudaFuncAttributeMaxDynamicSharedMemorySize, MM4_SMEM);
    cudaFuncSetAttribute(mm4<2>, cudaFuncAttributeMaxDynamicSharedMemorySize, MM4_SMEM);
    cudaFuncSetAttribute(mm4<3>, cudaFuncAttributeMaxDynamicSharedMemorySize, MM4_SMEM);
    cudaFuncSetAttribute(hx_attn16, cudaFuncAttributeMaxDynamicSharedMemorySize, AT_SMEM);

    // 0) weight fp16 conversion
    hx_wsplit<<<4096, 256>>>(q_w, k_w, v_w, o_w, w1, w2, p_wh);

    // 1) LN1 -> xn fp16
    hx_ln<<<M_, 256>>>(acts_in, ln1_w, p_xnh);

    // 2) fused QKV projection + xPos rope + transpose -> fp16 qt/kt/vt
    mm4<3><<<64*48, 256, MM4_SMEM>>>(M_, HID_, HID_,
        p_xnh, p_wh, nullptr, nullptr, nullptr,
        p_qt, p_kt, p_vt, p_index, 48);

    // 3) fp16 tensor-core causal flash attention -> ctx fp16 (longest-first)
    hx_attn16<<<dim3(B_*H_, S_/128), 256, AT_SMEM>>>(p_qt, p_kt, p_vt, p_ctxh);

    // 4) O projection + residual -> acts fp32
    mm4<1><<<64*16, 256, MM4_SMEM>>>(M_, HID_, HID_,
        p_ctxh, p_wh + OFF_O, acts_in, p_acts, nullptr,
        nullptr, nullptr, nullptr, nullptr, 16);

    // 5) LN2 -> xn fp16 (reuse)
    hx_ln<<<M_, 256>>>(p_acts, ln2_w, p_xnh);

    // 6) FFN up + exact GELU -> h fp16
    mm4<2><<<64*64, 256, MM4_SMEM>>>(M_, FF_, HID_,
        p_xnh, p_wh + OFF_W1, nullptr, nullptr, p_hh,
        nullptr, nullptr, nullptr, nullptr, 64);

    // 7) FFN down + residual -> output acts
    mm4<1><<<64*16, 256, MM4_SMEM>>>(M_, HID_, FF_,
        p_hh, p_wh + OFF_W2, p_acts, out, nullptr,
        nullptr, nullptr, nullptr, nullptr, 16);

    // 8) pass-through caches
    const long actN = (long)M_*HID_;
    if (n_in > 2 && (long)out_size >= actN + (long)in_sizes[1] + (long)in_sizes[2]) {
        cudaMemcpyAsync(out + actN, d_in[1],
                        (size_t)in_sizes[1]*sizeof(float),
                        cudaMemcpyDeviceToDevice);
        cudaMemcpyAsync(out + actN + in_sizes[1], d_in[2],
                        (size_t)in_sizes[2]*sizeof(float),
                        cudaMemcpyDeviceToDevice);
    }
}